// round 12
// baseline (speedup 1.0000x reference)
#include <cuda_runtime.h>
#include <cuda_bf16.h>
#include <math.h>

#define E_NUM 100000
#define NN 5000

// ---------------- packed (bf16 hi/lo) scratch: word = pair along contraction dim ----------------
__device__ __align__(16) unsigned g_h0H[E_NUM * 128];
__device__ __align__(16) unsigned g_h0L[E_NUM * 128];
__device__ __align__(16) unsigned g_h1H[E_NUM * 128];
__device__ __align__(16) unsigned g_h1L[E_NUM * 128];
__device__ __align__(16) unsigned g_latH[E_NUM * 128];
__device__ __align__(16) unsigned g_latL[E_NUM * 128];
__device__ __align__(16) unsigned g_tsH[E_NUM * 64];
__device__ __align__(16) unsigned g_tsL[E_NUM * 64];
__device__ __align__(16) unsigned g_tvH[3 * E_NUM * 64];
__device__ __align__(16) unsigned g_tvL[3 * E_NUM * 64];
// weight arena (pre-split B operands)
__device__ __align__(16) unsigned g_BH[320000];
__device__ __align__(16) unsigned g_BL[320000];
// fp32 scratch
__device__ __align__(16) float g_An[NN * 256];
__device__ __align__(16) float g_Bn[NN * 256];
__device__ __align__(16) float g_cut[E_NUM];
__device__ __align__(16) float g_lat[E_NUM * 256];
__device__ __align__(16) float g_wall[E_NUM * 192];
__device__ __align__(16) float g_fs1[E_NUM * 64];
__device__ __align__(16) float g_fv1[3 * E_NUM * 64];
__device__ __align__(16) float g_ns[NN * 64];
__device__ __align__(16) float g_nv[3 * NN * 64];
__device__ __align__(16) float g_ns2[NN * 64];
__device__ __align__(16) float g_nv2[3 * NN * 64];
__device__ __align__(16) float g_fs3[E_NUM * 128];

// arena offsets (words)
#define OFF_NA 0
#define OFF_NB 8192
#define OFF_TB1 16384
#define OFF_TB2 49152
#define OFF_ENV0 81920
#define OFF_ENV1 122880
#define OFF_L0S 147456
#define OFF_L0V 151552
#define OFF_LA0 155648
#define OFF_LA1 204800
#define OFF_SW1 237568
#define OFF_VW1 245760
#define OFF_F0 253952
#define OFF_F1 303104

__device__ __forceinline__ float siluf(float x) { return x / (1.0f + expf(-x)); }

__device__ __forceinline__ void bsplit(float x, unsigned short& hb, unsigned short& lb)
{
    __nv_bfloat16 h = __float2bfloat16(x);
    hb = __bfloat16_as_ushort(h);
    float hf = __uint_as_float((unsigned)hb << 16);
    lb = __bfloat16_as_ushort(__float2bfloat16(x - hf));
}
__device__ __forceinline__ unsigned pack16(unsigned short lo, unsigned short hi)
{
    return (unsigned)lo | ((unsigned)hi << 16);
}
__device__ __forceinline__ void packpair(float v0, float v1, unsigned& H, unsigned& L)
{
    unsigned short h0, l0, h1, l1;
    bsplit(v0, h0, l0);
    bsplit(v1, h1, l1);
    H = pack16(h0, h1);
    L = pack16(l0, l1);
}

#define MMA_BF16(ACC, A0, A1, A2, A3, B0, B1)                                     \
    asm volatile(                                                                 \
        "mma.sync.aligned.m16n8k16.row.col.f32.bf16.bf16.f32 "                    \
        "{%0,%1,%2,%3},{%4,%5,%6,%7},{%8,%9},{%0,%1,%2,%3};"                      \
        : "+f"((ACC)[0]), "+f"((ACC)[1]), "+f"((ACC)[2]), "+f"((ACC)[3])          \
        : "r"(A0), "r"(A1), "r"(A2), "r"(A3), "r"(B0), "r"(B1))

#define LDSM4(R, ADDR)                                                            \
    asm volatile("ldmatrix.sync.aligned.m8n8.x4.shared.b16 {%0,%1,%2,%3},[%4];"   \
                 : "=r"((R)[0]), "=r"((R)[1]), "=r"((R)[2]), "=r"((R)[3])         \
                 : "r"(ADDR))

#define LDSM4T(R0, R1, R2, R3, ADDR)                                              \
    asm volatile("ldmatrix.sync.aligned.m8n8.x4.trans.shared.b16 "                \
                 "{%0,%1,%2,%3},[%4];"                                            \
                 : "=r"(R0), "=r"(R1), "=r"(R2), "=r"(R3)                         \
                 : "r"(ADDR))

// ============ 3xBF16 GEMM with pre-split operands ============
// ASPLIT=1: A given as packed hi/lo word arrays (word = k-pair), stride Kw=K/2.
// ASPLIT=0: A fp32 (node_attrs), split in-kernel. B always pre-split (BH/BL, word stride Nw).
// EPI: 0 fp32 C, 1 silu->packed CH/CL, 2 cut*acc->fp32 C + packed, 3 residual(read fp32 C)->packed,
//      4 out=acc*aux, 5 strided vec out, 6 env-scatter atomics.
template <int BN, int EPI, int ASPLIT>
__global__ void __launch_bounds__(256, (BN == 64) ? 3 : 2) gemm_tc(
    const void* A1a, const void* A1b, int K1,
    const unsigned* __restrict__ A2H, const unsigned* __restrict__ A2L, int K2,
    const unsigned* __restrict__ BH, const unsigned* __restrict__ BL, int Nw,
    float* C, unsigned* CH, unsigned* CL,
    int M, const float* __restrict__ caux, const float* __restrict__ res_p,
    long strideAw, long strideC,
    const int* __restrict__ centers, const float* __restrict__ angp, int Cld)
{
    constexpr int BM = 128, BK = 32;
    constexpr int WM = (BN == 64) ? 32 : 64;
    constexpr int MT = WM / 16;
    constexpr int NT = 4;
    constexpr int NWM = BM / WM;
    constexpr int AW = 20;
    constexpr int BW = BN / 2 + 4;
    constexpr int ASZ = 2 * BM * AW;
    constexpr int BSZ = 2 * BK * BW;
    constexpr int F4W = BN / 8;            // uint4 units per B row: 16 or 8
    constexpr int RPPB = 256 / F4W;        // rows per pass: 16 or 32
    constexpr int NPB = BK / RPPB;         // passes: 2 or 1

    extern __shared__ unsigned smu[];
    unsigned* AsH = smu;
    unsigned* AsL = smu + ASZ;
    unsigned* BsH = smu + 2 * ASZ;
    unsigned* BsL = smu + 2 * ASZ + BSZ;
    const unsigned baseAH = (unsigned)__cvta_generic_to_shared(AsH);
    const unsigned baseAL = (unsigned)__cvta_generic_to_shared(AsL);
    const unsigned baseBH = (unsigned)__cvta_generic_to_shared(BsH);
    const unsigned baseBL = (unsigned)__cvta_generic_to_shared(BsL);

    const int comp = blockIdx.z;
    const unsigned* A1H = (const unsigned*)A1a + (size_t)comp * strideAw;
    const unsigned* A1L = (const unsigned*)A1b + (size_t)comp * strideAw;
    const float* A1F = (const float*)A1a;
    C += (size_t)comp * ((EPI == 5) ? 1 : strideC);

    const int tid = threadIdx.x;
    const int lane = tid & 31;
    const int warp = tid >> 5;
    const int g = lane >> 2;
    const int kq = lane & 3;
    const int wm = warp & (NWM - 1);
    const int wn = warp / NWM;
    const int m0 = blockIdx.y * BM;
    const int n0w = blockIdx.x * (BN / 2);
    const int K = K1 + K2;
    const int T = K / BK;

    const int arow = (lane & 7) + ((lane >> 3) & 1) * 8;
    const int akoff = (lane >> 4) * 4;
    const int brow = (lane & 7) + ((lane >> 3) & 1) * 8;
    const int bnoff = (lane >> 4) * 4;

    float acc[MT][NT][4];
#pragma unroll
    for (int i = 0; i < MT; i++)
#pragma unroll
        for (int j = 0; j < NT; j++)
#pragma unroll
            for (int q = 0; q < 4; q++) acc[i][j][q] = 0.0f;

    uint4 aSH[2], aSL[2], bSH[NPB], bSL[NPB];
    float4 aF[4];

    auto loadRegs = [&](int kt) {
        int k0 = kt * BK;
        if (ASPLIT) {
            const unsigned *AH, *AL;
            int Kw, k0w;
            if (k0 < K1) { AH = A1H; AL = A1L; Kw = K1 >> 1; k0w = k0 >> 1; }
            else { AH = A2H; AL = A2L; Kw = K2 >> 1; k0w = (k0 - K1) >> 1; }
            int wc = (tid & 3) * 4;
            int rb = tid >> 2;
#pragma unroll
            for (int p = 0; p < 2; p++) {
                int gm = m0 + rb + p * 64;
                if (gm < M) {
                    aSH[p] = *reinterpret_cast<const uint4*>(&AH[(size_t)gm * Kw + k0w + wc]);
                    aSL[p] = *reinterpret_cast<const uint4*>(&AL[(size_t)gm * Kw + k0w + wc]);
                } else {
                    aSH[p] = make_uint4(0, 0, 0, 0);
                    aSL[p] = make_uint4(0, 0, 0, 0);
                }
            }
        } else {
            int ac = (tid & 7) * 4;
            int rb = tid >> 3;
#pragma unroll
            for (int p = 0; p < 4; p++) {
                int gm = m0 + rb + p * 32;
                aF[p] = (gm < M) ? *reinterpret_cast<const float4*>(&A1F[(size_t)gm * K1 + k0 + ac])
                                 : make_float4(0.f, 0.f, 0.f, 0.f);
            }
        }
#pragma unroll
        for (int p = 0; p < NPB; p++) {
            int r = tid / F4W + p * RPPB;
            int c4 = (tid % F4W) * 4;
            bSH[p] = *reinterpret_cast<const uint4*>(&BH[(size_t)(k0 + r) * Nw + n0w + c4]);
            bSL[p] = *reinterpret_cast<const uint4*>(&BL[(size_t)(k0 + r) * Nw + n0w + c4]);
        }
    };
    auto storeStage = [&](int buf) {
        if (ASPLIT) {
            int wc = (tid & 3) * 4;
            int rb = tid >> 2;
#pragma unroll
            for (int p = 0; p < 2; p++) {
                int off = (buf * BM + rb + p * 64) * AW + wc;
                *reinterpret_cast<uint4*>(&AsH[off]) = aSH[p];
                *reinterpret_cast<uint4*>(&AsL[off]) = aSL[p];
            }
        } else {
            int ac = (tid & 7) * 4;
            int rb = tid >> 3;
#pragma unroll
            for (int p = 0; p < 4; p++) {
                const float* v = reinterpret_cast<const float*>(&aF[p]);
                unsigned short h[4], l[4];
#pragma unroll
                for (int j = 0; j < 4; j++) bsplit(v[j], h[j], l[j]);
                int off = (buf * BM + rb + p * 32) * AW + (ac >> 1);
                *reinterpret_cast<uint2*>(&AsH[off]) = make_uint2(pack16(h[0], h[1]), pack16(h[2], h[3]));
                *reinterpret_cast<uint2*>(&AsL[off]) = make_uint2(pack16(l[0], l[1]), pack16(l[2], l[3]));
            }
        }
#pragma unroll
        for (int p = 0; p < NPB; p++) {
            int r = tid / F4W + p * RPPB;
            int c4 = (tid % F4W) * 4;
            int off = (buf * BK + r) * BW + c4;
            *reinterpret_cast<uint4*>(&BsH[off]) = bSH[p];
            *reinterpret_cast<uint4*>(&BsL[off]) = bSL[p];
        }
    };
    auto compute = [&](int buf) {
#pragma unroll
        for (int ks = 0; ks < 2; ks++) {
            unsigned ah[MT][4], al[MT][4], bh[NT][2], bl[NT][2];
#pragma unroll
            for (int mt = 0; mt < MT; mt++) {
                unsigned offA = (unsigned)(((buf * BM + wm * WM + mt * 16 + arow) * AW
                                            + ks * 8 + akoff) * 4);
                LDSM4(ah[mt], baseAH + offA);
                LDSM4(al[mt], baseAL + offA);
            }
#pragma unroll
            for (int q = 0; q < 2; q++) {
                unsigned offB = (unsigned)(((buf * BK + ks * 16 + brow) * BW
                                            + wn * 16 + q * 8 + bnoff) * 4);
                LDSM4T(bh[2 * q][0], bh[2 * q][1], bh[2 * q + 1][0], bh[2 * q + 1][1],
                       baseBH + offB);
                LDSM4T(bl[2 * q][0], bl[2 * q][1], bl[2 * q + 1][0], bl[2 * q + 1][1],
                       baseBL + offB);
            }
#pragma unroll
            for (int mt = 0; mt < MT; mt++)
#pragma unroll
                for (int nt = 0; nt < NT; nt++) {
                    MMA_BF16(acc[mt][nt], al[mt][0], al[mt][1], al[mt][2], al[mt][3],
                             bh[nt][0], bh[nt][1]);
                    MMA_BF16(acc[mt][nt], ah[mt][0], ah[mt][1], ah[mt][2], ah[mt][3],
                             bl[nt][0], bl[nt][1]);
                    MMA_BF16(acc[mt][nt], ah[mt][0], ah[mt][1], ah[mt][2], ah[mt][3],
                             bh[nt][0], bh[nt][1]);
                }
        }
    };

    loadRegs(0);
    storeStage(0);
    __syncthreads();
    for (int t = 0; t < T; t++) {
        bool more = (t + 1 < T);
        if (more) loadRegs(t + 1);
        compute(t & 1);
        if (more) storeStage((t + 1) & 1);
        __syncthreads();
    }

    float rc1 = 0.f, rc2 = 0.f;
    if (EPI == 3) {
        float av = 1.0f / (1.0f + expf(-res_p[1]));
        rc1 = sqrtf(1.0f - av);
        rc2 = sqrtf(av);
    }
#pragma unroll
    for (int mt = 0; mt < MT; mt++) {
#pragma unroll
        for (int h = 0; h < 2; h++) {
            int row = m0 + wm * WM + mt * 16 + g + h * 8;
            if (row >= M) continue;
            float rs = (EPI == 2 || EPI == 3) ? caux[row] : 0.0f;
            int cnode = 0;
            float4 sh = make_float4(0.f, 0.f, 0.f, 0.f);
            if (EPI == 6) {
                cnode = centers[row];
                sh = *reinterpret_cast<const float4*>(&angp[(size_t)row * 4]);
            }
#pragma unroll
            for (int nt = 0; nt < NT; nt++) {
                int col = n0w * 2 + wn * 32 + nt * 8 + kq * 2;
                float v0 = acc[mt][nt][2 * h];
                float v1 = acc[mt][nt][2 * h + 1];
                if (EPI == 6) {
                    int u = col >> 1;
                    atomicAdd(&g_ns[cnode * 64 + u], v0 * sh.x);
                    atomicAdd(&g_nv[cnode * 64 + u], v1 * sh.y);
                    atomicAdd(&g_nv[NN * 64 + cnode * 64 + u], v1 * sh.z);
                    atomicAdd(&g_nv[2 * NN * 64 + cnode * 64 + u], v1 * sh.w);
                    continue;
                }
                if (EPI == 1) {
                    v0 = siluf(v0);
                    v1 = siluf(v1);
                    unsigned H, L;
                    packpair(v0, v1, H, L);
                    size_t w = (size_t)row * (Cld >> 1) + (col >> 1);
                    CH[w] = H;
                    CL[w] = L;
                } else if (EPI == 2) {
                    v0 *= rs;
                    v1 *= rs;
                    *reinterpret_cast<float2*>(&C[(size_t)row * Cld + col]) = make_float2(v0, v1);
                    unsigned H, L;
                    packpair(v0, v1, H, L);
                    size_t w = (size_t)row * (Cld >> 1) + (col >> 1);
                    CH[w] = H;
                    CL[w] = L;
                } else if (EPI == 3) {
                    float2 o = *reinterpret_cast<const float2*>(&C[(size_t)row * Cld + col]);
                    v0 = rc1 * o.x + rc2 * rs * v0;
                    v1 = rc1 * o.y + rc2 * rs * v1;
                    unsigned H, L;
                    packpair(v0, v1, H, L);
                    size_t w = (size_t)row * (Cld >> 1) + (col >> 1);
                    CH[w] = H;
                    CL[w] = L;
                } else if (EPI == 4) {
                    float s0 = caux[(size_t)row * 128 + col];
                    float s1 = caux[(size_t)row * 128 + col + 1];
                    *reinterpret_cast<float2*>(&C[(size_t)row * 512 + col]) = make_float2(v0 * s0, v1 * s1);
                } else if (EPI == 5) {
                    size_t b = (size_t)row * 512 + 128 + (size_t)col * 3;
                    C[b] = v0;
                    C[b + 3] = v1;
                } else {
                    *reinterpret_cast<float2*>(&C[(size_t)row * Cld + col]) = make_float2(v0, v1);
                }
            }
        }
    }
}

// ---------------- weight pre-split ----------------
__global__ void k_wprep(const float* __restrict__ W, unsigned* __restrict__ H,
                        unsigned* __restrict__ L, int words, int halfN)
{
    int idx = blockIdx.x * 256 + threadIdx.x;
    if (idx >= words) return;
    int k = idx / halfN;
    int c = idx - k * halfN;
    unsigned hw, lw;
    packpair(W[(size_t)k * 2 * halfN + 2 * c], W[(size_t)k * 2 * halfN + 2 * c + 1], hw, lw);
    H[idx] = hw;
    L[idx] = lw;
}

// lin1 weights (2,2,64,64) -> packed (128 rows)(64 words)
__global__ void k_prep1(const float* __restrict__ sw, const float* __restrict__ vw)
{
    int idx = blockIdx.x * 256 + threadIdx.x;
    if (idx >= 128 * 64) return;
    int r = idx >> 6, c = idx & 63;
    int i = r >> 6, u = r & 63;
    int col0 = 2 * c;
    int o = col0 >> 6, v = col0 & 63;
    size_t s = ((size_t)(i * 2 + o) * 64 + u) * 64 + v;
    unsigned hw, lw;
    packpair(sw[s], sw[s + 1], hw, lw);
    g_BH[OFF_SW1 + idx] = hw;
    g_BL[OFF_SW1 + idx] = lw;
    packpair(vw[s], vw[s + 1], hw, lw);
    g_BH[OFF_VW1 + idx] = hw;
    g_BL[OFF_VW1 + idx] = lw;
}

// ---------------- first layer (packed h0 out) ----------------
__global__ void k_first(const float* __restrict__ radial, const float* __restrict__ elen,
                        const int* __restrict__ eidx, const float* __restrict__ w0r)
{
    int e = blockIdx.x;
    int t = threadIdx.x;  // 128
    __shared__ float r[8];
    if (t < 8) r[t] = radial[e * 8 + t];
    if (t == 0) {
        float x = elen[e] * 0.2f;
        float x2 = x * x;
        float x6 = x2 * x2 * x2;
        float o = 1.0f - 28.0f * x6 + 48.0f * x6 * x - 21.0f * x6 * x2;
        g_cut[e] = (x < 1.0f) ? o : 0.0f;
    }
    __syncthreads();
    int c = eidx[e];
    int n = eidx[E_NUM + e];
    float a0 = g_An[c * 256 + 2 * t] + g_Bn[n * 256 + 2 * t];
    float a1 = g_An[c * 256 + 2 * t + 1] + g_Bn[n * 256 + 2 * t + 1];
#pragma unroll
    for (int j = 0; j < 8; j++) {
        a0 = fmaf(r[j], w0r[j * 256 + 2 * t], a0);
        a1 = fmaf(r[j], w0r[j * 256 + 2 * t + 1], a1);
    }
    unsigned H, L;
    packpair(siluf(a0), siluf(a1), H, L);
    g_h0H[(size_t)e * 128 + t] = H;
    g_h0L[(size_t)e * 128 + t] = L;
}

__global__ void k_zero()
{
    int i = blockIdx.x * 256 + threadIdx.x;
    if (i < NN * 64) {
        g_ns[i] = 0.f;
        g_nv[i] = 0.f;
        g_nv[NN * 64 + i] = 0.f;
        g_nv[2 * NN * 64 + i] = 0.f;
    }
}

__global__ void k_nodelin(const float* __restrict__ W)
{
    int nn = blockIdx.x;
    int t = threadIdx.x;
    __shared__ float sin_[256];
    int ch = t >> 6, v = t & 63;
    float val = (ch == 0) ? g_ns[nn * 64 + v] : g_nv[(ch - 1) * NN * 64 + nn * 64 + v];
    sin_[t] = val * 0.05f;
    __syncthreads();
    const float* Wm = W + (ch == 0 ? 0 : 64 * 64);
    float acc = 0.f;
#pragma unroll
    for (int u = 0; u < 64; u++) acc = fmaf(sin_[ch * 64 + u], Wm[u * 64 + v], acc);
    if (ch == 0) g_ns2[nn * 64 + v] = acc;
    else g_nv2[(ch - 1) * NN * 64 + nn * 64 + v] = acc;
}

// ---------------- TP tail: pack pair (u0=2c, u1=2c+1) into ts/tv words ----------------
__device__ __forceinline__ void tp_pack(int e, int c, int cn,
                                        float f0, float fx0, float fy0, float fz0,
                                        float f1, float fx1, float fy1, float fz1)
{
    const float IS3 = 0.57735026918962576f;
    int u0 = 2 * c, u1 = 2 * c + 1;
    float s20 = g_ns2[cn * 64 + u0], s21 = g_ns2[cn * 64 + u1];
    float vx0 = g_nv2[cn * 64 + u0], vx1 = g_nv2[cn * 64 + u1];
    float vy0 = g_nv2[NN * 64 + cn * 64 + u0], vy1 = g_nv2[NN * 64 + cn * 64 + u1];
    float vz0 = g_nv2[2 * NN * 64 + cn * 64 + u0], vz1 = g_nv2[2 * NN * 64 + cn * 64 + u1];
    size_t b = (size_t)e * 64 + c;
    unsigned H, L;
    packpair(f0 * s20, f1 * s21, H, L);
    g_tsH[b] = H; g_tsL[b] = L;
    packpair((fx0 * vx0 + fy0 * vy0 + fz0 * vz0) * IS3,
             (fx1 * vx1 + fy1 * vy1 + fz1 * vz1) * IS3, H, L);
    g_tsH[b + 32] = H; g_tsL[b + 32] = L;
    packpair(f0 * vx0 * IS3, f1 * vx1 * IS3, H, L);
    g_tvH[b] = H; g_tvL[b] = L;
    packpair(fx0 * s20 * IS3, fx1 * s21 * IS3, H, L);
    g_tvH[b + 32] = H; g_tvL[b + 32] = L;
    packpair(f0 * vy0 * IS3, f1 * vy1 * IS3, H, L);
    g_tvH[(size_t)E_NUM * 64 + b] = H; g_tvL[(size_t)E_NUM * 64 + b] = L;
    packpair(fy0 * s20 * IS3, fy1 * s21 * IS3, H, L);
    g_tvH[(size_t)E_NUM * 64 + b + 32] = H; g_tvL[(size_t)E_NUM * 64 + b + 32] = L;
    packpair(f0 * vz0 * IS3, f1 * vz1 * IS3, H, L);
    g_tvH[(size_t)2 * E_NUM * 64 + b] = H; g_tvL[(size_t)2 * E_NUM * 64 + b] = L;
    packpair(fz0 * s20 * IS3, fz1 * s21 * IS3, H, L);
    g_tvH[(size_t)2 * E_NUM * 64 + b + 32] = H; g_tvL[(size_t)2 * E_NUM * 64 + b + 32] = L;
}

// stage0: wall 192 cols: [0:64) gate, [64:192) w_feat pairs
__global__ void k_tp0(const float* __restrict__ ang, const int* __restrict__ center)
{
    int idx = blockIdx.x * blockDim.x + threadIdx.x;
    if (idx >= E_NUM * 32) return;
    int e = idx >> 5, c = idx & 31;
    int u0 = 2 * c, u1 = 2 * c + 1;
    float4 sh = *reinterpret_cast<const float4*>(&ang[e * 4]);
    const float* w = &g_wall[(size_t)e * 192];
    float gt0 = w[u0], gt1 = w[u1];
    float wf00 = w[64 + 2 * u0], wf10 = w[65 + 2 * u0];
    float wf01 = w[64 + 2 * u1], wf11 = w[65 + 2 * u1];
    tp_pack(e, c, center[e],
            wf00 * sh.x * gt0, wf10 * sh.y * gt0, wf10 * sh.z * gt0, wf10 * sh.w * gt0,
            wf01 * sh.x * gt1, wf11 * sh.y * gt1, wf11 * sh.z * gt1, wf11 * sh.w * gt1);
}

// stage1: wall 64 cols = gate
__global__ void k_tp1(const float* __restrict__ ang, const int* __restrict__ center)
{
    int idx = blockIdx.x * blockDim.x + threadIdx.x;
    if (idx >= E_NUM * 32) return;
    int e = idx >> 5, c = idx & 31;
    int u0 = 2 * c, u1 = 2 * c + 1;
    float gt0 = g_wall[(size_t)e * 64 + u0], gt1 = g_wall[(size_t)e * 64 + u1];
    size_t b0 = (size_t)e * 64 + u0, b1 = (size_t)e * 64 + u1;
    tp_pack(e, c, center[e],
            g_fs1[b0] * gt0, g_fv1[b0] * gt0,
            g_fv1[E_NUM * 64 + b0] * gt0, g_fv1[2 * E_NUM * 64 + b0] * gt0,
            g_fs1[b1] * gt1, g_fv1[b1] * gt1,
            g_fv1[E_NUM * 64 + b1] * gt1, g_fv1[2 * E_NUM * 64 + b1] * gt1);
}

// ---------------- host launch ----------------
template <typename T>
static void* symaddr(const T& sym)
{
    void* p = nullptr;
    cudaGetSymbolAddress(&p, sym);
    return p;
}

static const int SMEM64 = (2 * (2 * 128 * 20) + 2 * (2 * 32 * 36)) * 4;   // 59392
static const int SMEM128 = (2 * (2 * 128 * 20) + 2 * (2 * 32 * 68)) * 4;  // 75776

extern "C" void kernel_launch(void* const* d_in, const int* in_sizes, int n_in,
                              void* d_out, int out_size)
{
    const float* node_attrs = (const float*)d_in[0];
    const float* radial = (const float*)d_in[1];
    const float* ang = (const float*)d_in[2];
    const float* elen = (const float*)d_in[3];
    const int* eidx = (const int*)d_in[4];
    const float* tb_w0 = (const float*)d_in[5];
    const float* tb_w1 = (const float*)d_in[6];
    const float* tb_w2 = (const float*)d_in[7];
    const float* lat1_w0 = (const float*)d_in[8];
    const float* lat1_w1 = (const float*)d_in[9];
    const float* env0_w = (const float*)d_in[10];
    const float* env1_w = (const float*)d_in[11];
    const float* envlin0 = (const float*)d_in[12];
    const float* envlin1 = (const float*)d_in[13];
    const float* lin0_sw = (const float*)d_in[14];
    const float* lin0_vw = (const float*)d_in[15];
    const float* lin1_sw = (const float*)d_in[16];
    const float* lin1_vw = (const float*)d_in[17];
    const float* fin_w0 = (const float*)d_in[18];
    const float* fin_w1 = (const float*)d_in[19];
    const float* res_p = (const float*)d_in[20];
    float* out = (float*)d_out;

    float* An = (float*)symaddr(g_An);
    float* Bn = (float*)symaddr(g_Bn);
    float* cut = (float*)symaddr(g_cut);
    float* lat = (float*)symaddr(g_lat);
    float* wall = (float*)symaddr(g_wall);
    float* fs1 = (float*)symaddr(g_fs1);
    float* fv1 = (float*)symaddr(g_fv1);
    float* fs3 = (float*)symaddr(g_fs3);
    unsigned* h0H = (unsigned*)symaddr(g_h0H);
    unsigned* h0L = (unsigned*)symaddr(g_h0L);
    unsigned* h1H = (unsigned*)symaddr(g_h1H);
    unsigned* h1L = (unsigned*)symaddr(g_h1L);
    unsigned* latH = (unsigned*)symaddr(g_latH);
    unsigned* latL = (unsigned*)symaddr(g_latL);
    unsigned* tsH = (unsigned*)symaddr(g_tsH);
    unsigned* tsL = (unsigned*)symaddr(g_tsL);
    unsigned* tvH = (unsigned*)symaddr(g_tvH);
    unsigned* tvL = (unsigned*)symaddr(g_tvL);
    unsigned* BH = (unsigned*)symaddr(g_BH);
    unsigned* BL = (unsigned*)symaddr(g_BL);

    (void)in_sizes; (void)n_in; (void)out_size;

    cudaFuncSetAttribute(gemm_tc<128, 0, 0>, cudaFuncAttributeMaxDynamicSharedMemorySize, SMEM128);
    cudaFuncSetAttribute(gemm_tc<128, 0, 1>, cudaFuncAttributeMaxDynamicSharedMemorySize, SMEM128);
    cudaFuncSetAttribute(gemm_tc<128, 1, 1>, cudaFuncAttributeMaxDynamicSharedMemorySize, SMEM128);
    cudaFuncSetAttribute(gemm_tc<128, 2, 1>, cudaFuncAttributeMaxDynamicSharedMemorySize, SMEM128);
    cudaFuncSetAttribute(gemm_tc<128, 3, 1>, cudaFuncAttributeMaxDynamicSharedMemorySize, SMEM128);
    cudaFuncSetAttribute(gemm_tc<128, 4, 1>, cudaFuncAttributeMaxDynamicSharedMemorySize, SMEM128);
    cudaFuncSetAttribute(gemm_tc<128, 5, 1>, cudaFuncAttributeMaxDynamicSharedMemorySize, SMEM128);
    cudaFuncSetAttribute(gemm_tc<128, 6, 1>, cudaFuncAttributeMaxDynamicSharedMemorySize, SMEM128);
    cudaFuncSetAttribute(gemm_tc<64, 0, 1>, cudaFuncAttributeMaxDynamicSharedMemorySize, SMEM64);

    const int EW2 = (E_NUM * 32 + 255) / 256;
    const int ZB = (NN * 64 + 255) / 256;
    const long E64w = E_NUM * 64;

    auto wp = [&](const float* W, int off, int K, int N) {
        int words = K * N / 2;
        k_wprep<<<(words + 255) / 256, 256>>>(W, BH + off, BL + off, words, N / 2);
    };

    // weight pre-split
    wp(tb_w0, OFF_NA, 64, 256);
    wp(tb_w0 + 64 * 256, OFF_NB, 64, 256);
    wp(tb_w1, OFF_TB1, 256, 256);
    wp(tb_w2, OFF_TB2, 256, 256);
    wp(env0_w, OFF_ENV0, 256, 320);
    wp(env1_w, OFF_ENV1, 256, 192);
    wp(lin0_sw, OFF_L0S, 128, 64);
    wp(lin0_vw, OFF_L0V, 128, 64);
    wp(lat1_w0, OFF_LA0, 384, 256);
    wp(lat1_w1, OFF_LA1, 256, 256);
    wp(fin_w0, OFF_F0, 384, 256);
    wp(fin_w1, OFF_F1, 256, 128);
    k_prep1<<<(128 * 64 + 255) / 256, 256>>>(lin1_sw, lin1_vw);

    // node precompute (A fp32)
    gemm_tc<128, 0, 0><<<dim3(2, 40, 1), 256, SMEM128>>>(node_attrs, nullptr, 64, nullptr, nullptr, 0,
        BH + OFF_NA, BL + OFF_NA, 128, An, nullptr, nullptr, NN, nullptr, nullptr, 0, 0, nullptr, nullptr, 256);
    gemm_tc<128, 0, 0><<<dim3(2, 40, 1), 256, SMEM128>>>(node_attrs, nullptr, 64, nullptr, nullptr, 0,
        BH + OFF_NB, BL + OFF_NB, 128, Bn, nullptr, nullptr, NN, nullptr, nullptr, 0, 0, nullptr, nullptr, 256);

    // first layer + cut (packed h0)
    k_first<<<E_NUM, 128>>>(radial, elen, eidx, tb_w0 + 128 * 256);

    // tb MLP
    gemm_tc<128, 1, 1><<<dim3(2, 782, 1), 256, SMEM128>>>(h0H, h0L, 256, nullptr, nullptr, 0,
        BH + OFF_TB1, BL + OFF_TB1, 128, nullptr, h1H, h1L, E_NUM, nullptr, nullptr, 0, 0, nullptr, nullptr, 256);
    gemm_tc<128, 2, 1><<<dim3(2, 782, 1), 256, SMEM128>>>(h1H, h1L, 256, nullptr, nullptr, 0,
        BH + OFF_TB2, BL + OFF_TB2, 128, lat, latH, latL, E_NUM, cut, nullptr, 0, 0, nullptr, nullptr, 256);

    // env0: fused scatter (cols 0..127) + gate/feat store (cols 128..319 -> wall[0..191])
    k_zero<<<ZB, 256>>>();
    gemm_tc<128, 6, 1><<<dim3(1, 782, 1), 256, SMEM128>>>(latH, latL, 256, nullptr, nullptr, 0,
        BH + OFF_ENV0, BL + OFF_ENV0, 160, nullptr, nullptr, nullptr, E_NUM, nullptr, nullptr, 0, 0, eidx, ang, 256);
    gemm_tc<64, 0, 1><<<dim3(3, 782, 1), 256, SMEM64>>>(latH, latL, 256, nullptr, nullptr, 0,
        BH + OFF_ENV0 + 64, BL + OFF_ENV0 + 64, 160, wall, nullptr, nullptr, E_NUM, nullptr, nullptr, 0, 0, nullptr, nullptr, 192);
    k_nodelin<<<NN, 256>>>(envlin0);
    k_tp0<<<EW2, 256>>>(ang, eidx);

    // lin0 (N=64, packed ts/tv A)
    gemm_tc<64, 0, 1><<<dim3(1, 782, 1), 256, SMEM64>>>(tsH, tsL, 128, nullptr, nullptr, 0,
        BH + OFF_L0S, BL + OFF_L0S, 32, fs1, nullptr, nullptr, E_NUM, nullptr, nullptr, 0, 0, nullptr, nullptr, 64);
    gemm_tc<64, 0, 1><<<dim3(1, 782, 3), 256, SMEM64>>>(tvH, tvL, 128, nullptr, nullptr, 0,
        BH + OFF_L0V, BL + OFF_L0V, 32, fv1, nullptr, nullptr, E_NUM, nullptr, nullptr, E64w, E64w, nullptr, nullptr, 64);

    // lat1 MLP + residual
    gemm_tc<128, 1, 1><<<dim3(2, 782, 1), 256, SMEM128>>>(latH, latL, 256, tsH, tsL, 128,
        BH + OFF_LA0, BL + OFF_LA0, 128, nullptr, h1H, h1L, E_NUM, nullptr, nullptr, 0, 0, nullptr, nullptr, 256);
    gemm_tc<128, 3, 1><<<dim3(2, 782, 1), 256, SMEM128>>>(h1H, h1L, 256, nullptr, nullptr, 0,
        BH + OFF_LA1, BL + OFF_LA1, 128, lat, latH, latL, E_NUM, cut, res_p, 0, 0, nullptr, nullptr, 256);

    // env1
    k_zero<<<ZB, 256>>>();
    gemm_tc<128, 6, 1><<<dim3(1, 782, 1), 256, SMEM128>>>(latH, latL, 256, nullptr, nullptr, 0,
        BH + OFF_ENV1, BL + OFF_ENV1, 96, nullptr, nullptr, nullptr, E_NUM, nullptr, nullptr, 0, 0, eidx, ang, 256);
    gemm_tc<64, 0, 1><<<dim3(1, 782, 1), 256, SMEM64>>>(latH, latL, 256, nullptr, nullptr, 0,
        BH + OFF_ENV1 + 64, BL + OFF_ENV1 + 64, 96, wall, nullptr, nullptr, E_NUM, nullptr, nullptr, 0, 0, nullptr, nullptr, 64);
    k_nodelin<<<NN, 256>>>(envlin1);
    k_tp1<<<EW2, 256>>>(ang, eidx);

    // lin1: sw -> fs3; vw -> out vector half
    gemm_tc<128, 0, 1><<<dim3(1, 782, 1), 256, SMEM128>>>(tsH, tsL, 128, nullptr, nullptr, 0,
        BH + OFF_SW1, BL + OFF_SW1, 64, fs3, nullptr, nullptr, E_NUM, nullptr, nullptr, 0, 0, nullptr, nullptr, 128);
    gemm_tc<128, 5, 1><<<dim3(1, 782, 3), 256, SMEM128>>>(tvH, tvL, 128, nullptr, nullptr, 0,
        BH + OFF_VW1, BL + OFF_VW1, 64, out, nullptr, nullptr, E_NUM, nullptr, nullptr, E64w, 0, nullptr, nullptr, 128);

    // fin MLP
    gemm_tc<128, 1, 1><<<dim3(2, 782, 1), 256, SMEM128>>>(latH, latL, 256, tsH, tsL, 128,
        BH + OFF_F0, BL + OFF_F0, 128, nullptr, h1H, h1L, E_NUM, nullptr, nullptr, 0, 0, nullptr, nullptr, 256);
    gemm_tc<128, 4, 1><<<dim3(1, 782, 1), 256, SMEM128>>>(h1H, h1L, 256, nullptr, nullptr, 0,
        BH + OFF_F1, BL + OFF_F1, 64, out, nullptr, nullptr, E_NUM, fs3, nullptr, 0, 0, nullptr, nullptr, 128);
}

// round 13
// speedup vs baseline: 1.1525x; 1.1525x over previous
#include <cuda_runtime.h>
#include <cuda_bf16.h>
#include <math.h>

#define E_NUM 100000
#define NN 5000

// ---------------- packed (bf16 hi/lo) scratch ----------------
__device__ __align__(16) unsigned g_h0H[E_NUM * 128];
__device__ __align__(16) unsigned g_h0L[E_NUM * 128];
__device__ __align__(16) unsigned g_h1H[E_NUM * 128];
__device__ __align__(16) unsigned g_h1L[E_NUM * 128];
__device__ __align__(16) unsigned g_latH[E_NUM * 128];
__device__ __align__(16) unsigned g_latL[E_NUM * 128];
__device__ __align__(16) unsigned g_tsH[E_NUM * 64];
__device__ __align__(16) unsigned g_tsL[E_NUM * 64];
__device__ __align__(16) unsigned g_tvH[3 * E_NUM * 64];
__device__ __align__(16) unsigned g_tvL[3 * E_NUM * 64];
__device__ __align__(16) unsigned g_BH[320000];
__device__ __align__(16) unsigned g_BL[320000];
// fp32 scratch
__device__ __align__(16) float g_An[NN * 256];
__device__ __align__(16) float g_Bn[NN * 256];
__device__ __align__(16) float g_cut[E_NUM];
__device__ __align__(16) float g_lat[E_NUM * 256];
__device__ __align__(16) float g_wall[E_NUM * 192];
__device__ __align__(16) float g_fs1[E_NUM * 64];
__device__ __align__(16) float g_fv1[3 * E_NUM * 64];
__device__ __align__(16) float g_ns[NN * 64];
__device__ __align__(16) float g_nv[3 * NN * 64];
__device__ __align__(16) float g_ns2[NN * 64];
__device__ __align__(16) float g_nv2[3 * NN * 64];
__device__ __align__(16) float g_fs3[E_NUM * 128];

#define OFF_NA 0
#define OFF_NB 8192
#define OFF_TB1 16384
#define OFF_TB2 49152
#define OFF_ENV0 81920
#define OFF_ENV1 122880
#define OFF_L0S 147456
#define OFF_L0V 151552
#define OFF_LA0 155648
#define OFF_LA1 204800
#define OFF_SW1 237568
#define OFF_VW1 245760
#define OFF_F0 253952
#define OFF_F1 303104

__device__ __forceinline__ float siluf(float x) { return x / (1.0f + expf(-x)); }

__device__ __forceinline__ void bsplit(float x, unsigned short& hb, unsigned short& lb)
{
    __nv_bfloat16 h = __float2bfloat16(x);
    hb = __bfloat16_as_ushort(h);
    float hf = __uint_as_float((unsigned)hb << 16);
    lb = __bfloat16_as_ushort(__float2bfloat16(x - hf));
}
__device__ __forceinline__ unsigned pack16(unsigned short lo, unsigned short hi)
{
    return (unsigned)lo | ((unsigned)hi << 16);
}
__device__ __forceinline__ void packpair(float v0, float v1, unsigned& H, unsigned& L)
{
    unsigned short h0, l0, h1, l1;
    bsplit(v0, h0, l0);
    bsplit(v1, h1, l1);
    H = pack16(h0, h1);
    L = pack16(l0, l1);
}
__device__ __forceinline__ void cp16(unsigned d, const void* s, int sz)
{
    asm volatile("cp.async.cg.shared.global [%0], [%1], 16, %2;\n" :: "r"(d), "l"(s), "r"(sz));
}
__device__ __forceinline__ void cp_commit() { asm volatile("cp.async.commit_group;\n"); }
__device__ __forceinline__ void cp_wait0() { asm volatile("cp.async.wait_group 0;\n"); }

#define MMA_BF16(ACC, A0, A1, A2, A3, B0, B1)                                     \
    asm volatile(                                                                 \
        "mma.sync.aligned.m16n8k16.row.col.f32.bf16.bf16.f32 "                    \
        "{%0,%1,%2,%3},{%4,%5,%6,%7},{%8,%9},{%0,%1,%2,%3};"                      \
        : "+f"((ACC)[0]), "+f"((ACC)[1]), "+f"((ACC)[2]), "+f"((ACC)[3])          \
        : "r"(A0), "r"(A1), "r"(A2), "r"(A3), "r"(B0), "r"(B1))

#define LDSM4(R, ADDR)                                                            \
    asm volatile("ldmatrix.sync.aligned.m8n8.x4.shared.b16 {%0,%1,%2,%3},[%4];"   \
                 : "=r"((R)[0]), "=r"((R)[1]), "=r"((R)[2]), "=r"((R)[3])         \
                 : "r"(ADDR))

#define LDSM4T(R0, R1, R2, R3, ADDR)                                              \
    asm volatile("ldmatrix.sync.aligned.m8n8.x4.trans.shared.b16 "                \
                 "{%0,%1,%2,%3},[%4];"                                            \
                 : "=r"(R0), "=r"(R1), "=r"(R2), "=r"(R3)                         \
                 : "r"(ADDR))

// ============ 3xBF16 GEMM with pre-split operands ============
template <int BN, int EPI, int ASPLIT>
__global__ void __launch_bounds__(256, (BN == 64) ? 3 : 2) gemm_tc(
    const void* A1a, const void* A1b, int K1,
    const unsigned* __restrict__ A2H, const unsigned* __restrict__ A2L, int K2,
    const unsigned* __restrict__ BH, const unsigned* __restrict__ BL, int Nw,
    float* C, unsigned* CH, unsigned* CL,
    int M, const float* __restrict__ caux, const float* __restrict__ res_p,
    long strideAw, long strideC,
    const int* __restrict__ centers, const float* __restrict__ angp, int Cld)
{
    constexpr int BM = 128, BK = 32;
    constexpr int WM = (BN == 64) ? 32 : 64;
    constexpr int MT = WM / 16;
    constexpr int NT = 4;
    constexpr int NWM = BM / WM;
    constexpr int AW = 20;
    constexpr int BW = BN / 2 + 4;
    constexpr int ASZ = 2 * BM * AW;
    constexpr int BSZ = 2 * BK * BW;
    constexpr int F4W = BN / 8;
    constexpr int RPPB = 256 / F4W;
    constexpr int NPB = BK / RPPB;

    extern __shared__ unsigned smu[];
    unsigned* AsH = smu;
    unsigned* AsL = smu + ASZ;
    unsigned* BsH = smu + 2 * ASZ;
    unsigned* BsL = smu + 2 * ASZ + BSZ;
    const unsigned baseAH = (unsigned)__cvta_generic_to_shared(AsH);
    const unsigned baseAL = (unsigned)__cvta_generic_to_shared(AsL);
    const unsigned baseBH = (unsigned)__cvta_generic_to_shared(BsH);
    const unsigned baseBL = (unsigned)__cvta_generic_to_shared(BsL);

    const int comp = blockIdx.z;
    const unsigned* A1H = (const unsigned*)A1a + (size_t)comp * strideAw;
    const unsigned* A1L = (const unsigned*)A1b + (size_t)comp * strideAw;
    const float* A1F = (const float*)A1a;
    C += (size_t)comp * ((EPI == 5) ? 1 : strideC);

    const int tid = threadIdx.x;
    const int lane = tid & 31;
    const int warp = tid >> 5;
    const int g = lane >> 2;
    const int kq = lane & 3;
    const int wm = warp & (NWM - 1);
    const int wn = warp / NWM;
    const int m0 = blockIdx.y * BM;
    const int n0w = blockIdx.x * (BN / 2);
    const int K = K1 + K2;
    const int T = K / BK;

    const int arow = (lane & 7) + ((lane >> 3) & 1) * 8;
    const int akoff = (lane >> 4) * 4;
    const int brow = (lane & 7) + ((lane >> 3) & 1) * 8;
    const int bnoff = (lane >> 4) * 4;

    float acc[MT][NT][4];
#pragma unroll
    for (int i = 0; i < MT; i++)
#pragma unroll
        for (int j = 0; j < NT; j++)
#pragma unroll
            for (int q = 0; q < 4; q++) acc[i][j][q] = 0.0f;

    auto compute = [&](int buf) {
#pragma unroll
        for (int ks = 0; ks < 2; ks++) {
            unsigned ah[MT][4], al[MT][4], bh[NT][2], bl[NT][2];
#pragma unroll
            for (int mt = 0; mt < MT; mt++) {
                unsigned offA = (unsigned)(((buf * BM + wm * WM + mt * 16 + arow) * AW
                                            + ks * 8 + akoff) * 4);
                LDSM4(ah[mt], baseAH + offA);
                LDSM4(al[mt], baseAL + offA);
            }
#pragma unroll
            for (int q = 0; q < 2; q++) {
                unsigned offB = (unsigned)(((buf * BK + ks * 16 + brow) * BW
                                            + wn * 16 + q * 8 + bnoff) * 4);
                LDSM4T(bh[2 * q][0], bh[2 * q][1], bh[2 * q + 1][0], bh[2 * q + 1][1],
                       baseBH + offB);
                LDSM4T(bl[2 * q][0], bl[2 * q][1], bl[2 * q + 1][0], bl[2 * q + 1][1],
                       baseBL + offB);
            }
#pragma unroll
            for (int mt = 0; mt < MT; mt++)
#pragma unroll
                for (int nt = 0; nt < NT; nt++) {
                    MMA_BF16(acc[mt][nt], al[mt][0], al[mt][1], al[mt][2], al[mt][3],
                             bh[nt][0], bh[nt][1]);
                    MMA_BF16(acc[mt][nt], ah[mt][0], ah[mt][1], ah[mt][2], ah[mt][3],
                             bl[nt][0], bl[nt][1]);
                    MMA_BF16(acc[mt][nt], ah[mt][0], ah[mt][1], ah[mt][2], ah[mt][3],
                             bh[nt][0], bh[nt][1]);
                }
        }
    };

    if (ASPLIT) {
        // cp.async pipeline
        auto issue = [&](int kt, int buf) {
            int k0 = kt * BK;
            const unsigned *AH, *AL;
            int Kw, k0w;
            if (k0 < K1) { AH = A1H; AL = A1L; Kw = K1 >> 1; k0w = k0 >> 1; }
            else { AH = A2H; AL = A2L; Kw = K2 >> 1; k0w = (k0 - K1) >> 1; }
            int wc = (tid & 3) * 4;
            int rb = tid >> 2;
#pragma unroll
            for (int p = 0; p < 2; p++) {
                int row = rb + p * 64;
                int gm = m0 + row;
                int sz = (gm < M) ? 16 : 0;
                size_t so = (size_t)gm * Kw + k0w + wc;
                unsigned doff = (unsigned)(((buf * BM + row) * AW + wc) * 4);
                cp16(baseAH + doff, &AH[so], sz);
                cp16(baseAL + doff, &AL[so], sz);
            }
#pragma unroll
            for (int p = 0; p < NPB; p++) {
                int r = tid / F4W + p * RPPB;
                int c4 = (tid % F4W) * 4;
                size_t so = (size_t)(k0 + r) * Nw + n0w + c4;
                unsigned doff = (unsigned)(((buf * BK + r) * BW + c4) * 4);
                cp16(baseBH + doff, &BH[so], 16);
                cp16(baseBL + doff, &BL[so], 16);
            }
        };
        issue(0, 0);
        cp_commit();
        for (int t = 0; t < T; t++) {
            cp_wait0();
            __syncthreads();
            if (t + 1 < T) { issue(t + 1, (t + 1) & 1); cp_commit(); }
            compute(t & 1);
        }
    } else {
        // register-staged path (fp32 A, only used for tiny node GEMMs)
        float4 aF[4];
        uint4 bSH[NPB], bSL[NPB];
        auto loadRegs = [&](int kt) {
            int k0 = kt * BK;
            int ac = (tid & 7) * 4;
            int rb = tid >> 3;
#pragma unroll
            for (int p = 0; p < 4; p++) {
                int gm = m0 + rb + p * 32;
                aF[p] = (gm < M) ? *reinterpret_cast<const float4*>(&A1F[(size_t)gm * K1 + k0 + ac])
                                 : make_float4(0.f, 0.f, 0.f, 0.f);
            }
#pragma unroll
            for (int p = 0; p < NPB; p++) {
                int r = tid / F4W + p * RPPB;
                int c4 = (tid % F4W) * 4;
                bSH[p] = *reinterpret_cast<const uint4*>(&BH[(size_t)(k0 + r) * Nw + n0w + c4]);
                bSL[p] = *reinterpret_cast<const uint4*>(&BL[(size_t)(k0 + r) * Nw + n0w + c4]);
            }
        };
        auto storeStage = [&](int buf) {
            int ac = (tid & 7) * 4;
            int rb = tid >> 3;
#pragma unroll
            for (int p = 0; p < 4; p++) {
                const float* v = reinterpret_cast<const float*>(&aF[p]);
                unsigned short h[4], l[4];
#pragma unroll
                for (int j = 0; j < 4; j++) bsplit(v[j], h[j], l[j]);
                int off = (buf * BM + rb + p * 32) * AW + (ac >> 1);
                *reinterpret_cast<uint2*>(&AsH[off]) = make_uint2(pack16(h[0], h[1]), pack16(h[2], h[3]));
                *reinterpret_cast<uint2*>(&AsL[off]) = make_uint2(pack16(l[0], l[1]), pack16(l[2], l[3]));
            }
#pragma unroll
            for (int p = 0; p < NPB; p++) {
                int r = tid / F4W + p * RPPB;
                int c4 = (tid % F4W) * 4;
                int off = (buf * BK + r) * BW + c4;
                *reinterpret_cast<uint4*>(&BsH[off]) = bSH[p];
                *reinterpret_cast<uint4*>(&BsL[off]) = bSL[p];
            }
        };
        loadRegs(0);
        storeStage(0);
        __syncthreads();
        for (int t = 0; t < T; t++) {
            bool more = (t + 1 < T);
            if (more) loadRegs(t + 1);
            compute(t & 1);
            if (more) storeStage((t + 1) & 1);
            __syncthreads();
        }
    }

    float rc1 = 0.f, rc2 = 0.f;
    if (EPI == 3) {
        float av = 1.0f / (1.0f + expf(-res_p[1]));
        rc1 = sqrtf(1.0f - av);
        rc2 = sqrtf(av);
    }
#pragma unroll
    for (int mt = 0; mt < MT; mt++) {
#pragma unroll
        for (int h = 0; h < 2; h++) {
            int row = m0 + wm * WM + mt * 16 + g + h * 8;
            if (row >= M) continue;
            float rs = (EPI == 2 || EPI == 3) ? caux[row] : 0.0f;
            int cnode = 0;
            float4 sh = make_float4(0.f, 0.f, 0.f, 0.f);
            if (EPI == 6) {
                cnode = centers[row];
                sh = *reinterpret_cast<const float4*>(&angp[(size_t)row * 4]);
            }
#pragma unroll
            for (int nt = 0; nt < NT; nt++) {
                int col = n0w * 2 + wn * 32 + nt * 8 + kq * 2;
                float v0 = acc[mt][nt][2 * h];
                float v1 = acc[mt][nt][2 * h + 1];
                if (EPI == 6) {
                    int u = col >> 1;
                    atomicAdd(&g_ns[cnode * 64 + u], v0 * sh.x);
                    atomicAdd(&g_nv[cnode * 64 + u], v1 * sh.y);
                    atomicAdd(&g_nv[NN * 64 + cnode * 64 + u], v1 * sh.z);
                    atomicAdd(&g_nv[2 * NN * 64 + cnode * 64 + u], v1 * sh.w);
                    continue;
                }
                if (EPI == 1) {
                    v0 = siluf(v0);
                    v1 = siluf(v1);
                    unsigned H, L;
                    packpair(v0, v1, H, L);
                    size_t w = (size_t)row * (Cld >> 1) + (col >> 1);
                    CH[w] = H;
                    CL[w] = L;
                } else if (EPI == 2) {
                    v0 *= rs;
                    v1 *= rs;
                    *reinterpret_cast<float2*>(&C[(size_t)row * Cld + col]) = make_float2(v0, v1);
                    unsigned H, L;
                    packpair(v0, v1, H, L);
                    size_t w = (size_t)row * (Cld >> 1) + (col >> 1);
                    CH[w] = H;
                    CL[w] = L;
                } else if (EPI == 3) {
                    float2 o = *reinterpret_cast<const float2*>(&C[(size_t)row * Cld + col]);
                    v0 = rc1 * o.x + rc2 * rs * v0;
                    v1 = rc1 * o.y + rc2 * rs * v1;
                    unsigned H, L;
                    packpair(v0, v1, H, L);
                    size_t w = (size_t)row * (Cld >> 1) + (col >> 1);
                    CH[w] = H;
                    CL[w] = L;
                } else if (EPI == 4) {
                    float s0 = caux[(size_t)row * 128 + col];
                    float s1 = caux[(size_t)row * 128 + col + 1];
                    *reinterpret_cast<float2*>(&C[(size_t)row * 512 + col]) = make_float2(v0 * s0, v1 * s1);
                } else if (EPI == 5) {
                    size_t b = (size_t)row * 512 + 128 + (size_t)col * 3;
                    C[b] = v0;
                    C[b + 3] = v1;
                } else {
                    *reinterpret_cast<float2*>(&C[(size_t)row * Cld + col]) = make_float2(v0, v1);
                }
            }
        }
    }
}

// ---------------- fused weight pre-split (one launch) ----------------
struct WPEnt { const float* W; int off; int halfN; int words; };
struct WPArr { WPEnt e[12]; };

__global__ void k_wprep_all(WPArr arr)
{
    WPEnt e = arr.e[blockIdx.y];
    int idx = blockIdx.x * 256 + threadIdx.x;
    if (idx >= e.words) return;
    int k = idx / e.halfN;
    int c = idx - k * e.halfN;
    unsigned hw, lw;
    packpair(e.W[(size_t)k * 2 * e.halfN + 2 * c], e.W[(size_t)k * 2 * e.halfN + 2 * c + 1], hw, lw);
    g_BH[e.off + idx] = hw;
    g_BL[e.off + idx] = lw;
}

__global__ void k_prep1(const float* __restrict__ sw, const float* __restrict__ vw)
{
    int idx = blockIdx.x * 256 + threadIdx.x;
    if (idx >= 128 * 64) return;
    int r = idx >> 6, c = idx & 63;
    int i = r >> 6, u = r & 63;
    int col0 = 2 * c;
    int o = col0 >> 6, v = col0 & 63;
    size_t s = ((size_t)(i * 2 + o) * 64 + u) * 64 + v;
    unsigned hw, lw;
    packpair(sw[s], sw[s + 1], hw, lw);
    g_BH[OFF_SW1 + idx] = hw;
    g_BL[OFF_SW1 + idx] = lw;
    packpair(vw[s], vw[s + 1], hw, lw);
    g_BH[OFF_VW1 + idx] = hw;
    g_BL[OFF_VW1 + idx] = lw;
}

// ---------------- first layer (packed h0 out) ----------------
__global__ void k_first(const float* __restrict__ radial, const float* __restrict__ elen,
                        const int* __restrict__ eidx, const float* __restrict__ w0r)
{
    int e = blockIdx.x;
    int t = threadIdx.x;  // 128
    __shared__ float r[8];
    if (t < 8) r[t] = radial[e * 8 + t];
    if (t == 0) {
        float x = elen[e] * 0.2f;
        float x2 = x * x;
        float x6 = x2 * x2 * x2;
        float o = 1.0f - 28.0f * x6 + 48.0f * x6 * x - 21.0f * x6 * x2;
        g_cut[e] = (x < 1.0f) ? o : 0.0f;
    }
    __syncthreads();
    int c = eidx[e];
    int n = eidx[E_NUM + e];
    float a0 = g_An[c * 256 + 2 * t] + g_Bn[n * 256 + 2 * t];
    float a1 = g_An[c * 256 + 2 * t + 1] + g_Bn[n * 256 + 2 * t + 1];
#pragma unroll
    for (int j = 0; j < 8; j++) {
        a0 = fmaf(r[j], w0r[j * 256 + 2 * t], a0);
        a1 = fmaf(r[j], w0r[j * 256 + 2 * t + 1], a1);
    }
    unsigned H, L;
    packpair(siluf(a0), siluf(a1), H, L);
    g_h0H[(size_t)e * 128 + t] = H;
    g_h0L[(size_t)e * 128 + t] = L;
}

__global__ void k_zero()
{
    int i = blockIdx.x * 256 + threadIdx.x;
    if (i < NN * 64) {
        g_ns[i] = 0.f;
        g_nv[i] = 0.f;
        g_nv[NN * 64 + i] = 0.f;
        g_nv[2 * NN * 64 + i] = 0.f;
    }
}

__global__ void k_nodelin(const float* __restrict__ W)
{
    int nn = blockIdx.x;
    int t = threadIdx.x;
    __shared__ float sin_[256];
    int ch = t >> 6, v = t & 63;
    float val = (ch == 0) ? g_ns[nn * 64 + v] : g_nv[(ch - 1) * NN * 64 + nn * 64 + v];
    sin_[t] = val * 0.05f;
    __syncthreads();
    const float* Wm = W + (ch == 0 ? 0 : 64 * 64);
    float acc = 0.f;
#pragma unroll
    for (int u = 0; u < 64; u++) acc = fmaf(sin_[ch * 64 + u], Wm[u * 64 + v], acc);
    if (ch == 0) g_ns2[nn * 64 + v] = acc;
    else g_nv2[(ch - 1) * NN * 64 + nn * 64 + v] = acc;
}

__device__ __forceinline__ void tp_pack(int e, int c, int cn,
                                        float f0, float fx0, float fy0, float fz0,
                                        float f1, float fx1, float fy1, float fz1)
{
    const float IS3 = 0.57735026918962576f;
    int u0 = 2 * c, u1 = 2 * c + 1;
    float s20 = g_ns2[cn * 64 + u0], s21 = g_ns2[cn * 64 + u1];
    float vx0 = g_nv2[cn * 64 + u0], vx1 = g_nv2[cn * 64 + u1];
    float vy0 = g_nv2[NN * 64 + cn * 64 + u0], vy1 = g_nv2[NN * 64 + cn * 64 + u1];
    float vz0 = g_nv2[2 * NN * 64 + cn * 64 + u0], vz1 = g_nv2[2 * NN * 64 + cn * 64 + u1];
    size_t b = (size_t)e * 64 + c;
    unsigned H, L;
    packpair(f0 * s20, f1 * s21, H, L);
    g_tsH[b] = H; g_tsL[b] = L;
    packpair((fx0 * vx0 + fy0 * vy0 + fz0 * vz0) * IS3,
             (fx1 * vx1 + fy1 * vy1 + fz1 * vz1) * IS3, H, L);
    g_tsH[b + 32] = H; g_tsL[b + 32] = L;
    packpair(f0 * vx0 * IS3, f1 * vx1 * IS3, H, L);
    g_tvH[b] = H; g_tvL[b] = L;
    packpair(fx0 * s20 * IS3, fx1 * s21 * IS3, H, L);
    g_tvH[b + 32] = H; g_tvL[b + 32] = L;
    packpair(f0 * vy0 * IS3, f1 * vy1 * IS3, H, L);
    g_tvH[(size_t)E_NUM * 64 + b] = H; g_tvL[(size_t)E_NUM * 64 + b] = L;
    packpair(fy0 * s20 * IS3, fy1 * s21 * IS3, H, L);
    g_tvH[(size_t)E_NUM * 64 + b + 32] = H; g_tvL[(size_t)E_NUM * 64 + b + 32] = L;
    packpair(f0 * vz0 * IS3, f1 * vz1 * IS3, H, L);
    g_tvH[(size_t)2 * E_NUM * 64 + b] = H; g_tvL[(size_t)2 * E_NUM * 64 + b] = L;
    packpair(fz0 * s20 * IS3, fz1 * s21 * IS3, H, L);
    g_tvH[(size_t)2 * E_NUM * 64 + b + 32] = H; g_tvL[(size_t)2 * E_NUM * 64 + b + 32] = L;
}

__global__ void k_tp0(const float* __restrict__ ang, const int* __restrict__ center)
{
    int idx = blockIdx.x * blockDim.x + threadIdx.x;
    if (idx >= E_NUM * 32) return;
    int e = idx >> 5, c = idx & 31;
    int u0 = 2 * c, u1 = 2 * c + 1;
    float4 sh = *reinterpret_cast<const float4*>(&ang[e * 4]);
    const float* w = &g_wall[(size_t)e * 192];
    float gt0 = w[u0], gt1 = w[u1];
    float wf00 = w[64 + 2 * u0], wf10 = w[65 + 2 * u0];
    float wf01 = w[64 + 2 * u1], wf11 = w[65 + 2 * u1];
    tp_pack(e, c, center[e],
            wf00 * sh.x * gt0, wf10 * sh.y * gt0, wf10 * sh.z * gt0, wf10 * sh.w * gt0,
            wf01 * sh.x * gt1, wf11 * sh.y * gt1, wf11 * sh.z * gt1, wf11 * sh.w * gt1);
}

__global__ void k_tp1(const float* __restrict__ ang, const int* __restrict__ center)
{
    int idx = blockIdx.x * blockDim.x + threadIdx.x;
    if (idx >= E_NUM * 32) return;
    int e = idx >> 5, c = idx & 31;
    int u0 = 2 * c, u1 = 2 * c + 1;
    float gt0 = g_wall[(size_t)e * 64 + u0], gt1 = g_wall[(size_t)e * 64 + u1];
    size_t b0 = (size_t)e * 64 + u0, b1 = (size_t)e * 64 + u1;
    tp_pack(e, c, center[e],
            g_fs1[b0] * gt0, g_fv1[b0] * gt0,
            g_fv1[E_NUM * 64 + b0] * gt0, g_fv1[2 * E_NUM * 64 + b0] * gt0,
            g_fs1[b1] * gt1, g_fv1[b1] * gt1,
            g_fv1[E_NUM * 64 + b1] * gt1, g_fv1[2 * E_NUM * 64 + b1] * gt1);
}

// ---------------- host launch ----------------
template <typename T>
static void* symaddr(const T& sym)
{
    void* p = nullptr;
    cudaGetSymbolAddress(&p, sym);
    return p;
}

static const int SMEM64 = (2 * (2 * 128 * 20) + 2 * (2 * 32 * 36)) * 4;   // 59392
static const int SMEM128 = (2 * (2 * 128 * 20) + 2 * (2 * 32 * 68)) * 4;  // 75776

extern "C" void kernel_launch(void* const* d_in, const int* in_sizes, int n_in,
                              void* d_out, int out_size)
{
    const float* node_attrs = (const float*)d_in[0];
    const float* radial = (const float*)d_in[1];
    const float* ang = (const float*)d_in[2];
    const float* elen = (const float*)d_in[3];
    const int* eidx = (const int*)d_in[4];
    const float* tb_w0 = (const float*)d_in[5];
    const float* tb_w1 = (const float*)d_in[6];
    const float* tb_w2 = (const float*)d_in[7];
    const float* lat1_w0 = (const float*)d_in[8];
    const float* lat1_w1 = (const float*)d_in[9];
    const float* env0_w = (const float*)d_in[10];
    const float* env1_w = (const float*)d_in[11];
    const float* envlin0 = (const float*)d_in[12];
    const float* envlin1 = (const float*)d_in[13];
    const float* lin0_sw = (const float*)d_in[14];
    const float* lin0_vw = (const float*)d_in[15];
    const float* lin1_sw = (const float*)d_in[16];
    const float* lin1_vw = (const float*)d_in[17];
    const float* fin_w0 = (const float*)d_in[18];
    const float* fin_w1 = (const float*)d_in[19];
    const float* res_p = (const float*)d_in[20];
    float* out = (float*)d_out;

    float* An = (float*)symaddr(g_An);
    float* Bn = (float*)symaddr(g_Bn);
    float* cut = (float*)symaddr(g_cut);
    float* lat = (float*)symaddr(g_lat);
    float* wall = (float*)symaddr(g_wall);
    float* fs1 = (float*)symaddr(g_fs1);
    float* fv1 = (float*)symaddr(g_fv1);
    float* fs3 = (float*)symaddr(g_fs3);
    unsigned* h0H = (unsigned*)symaddr(g_h0H);
    unsigned* h0L = (unsigned*)symaddr(g_h0L);
    unsigned* h1H = (unsigned*)symaddr(g_h1H);
    unsigned* h1L = (unsigned*)symaddr(g_h1L);
    unsigned* latH = (unsigned*)symaddr(g_latH);
    unsigned* latL = (unsigned*)symaddr(g_latL);
    unsigned* tsH = (unsigned*)symaddr(g_tsH);
    unsigned* tsL = (unsigned*)symaddr(g_tsL);
    unsigned* tvH = (unsigned*)symaddr(g_tvH);
    unsigned* tvL = (unsigned*)symaddr(g_tvL);
    unsigned* BH = (unsigned*)symaddr(g_BH);
    unsigned* BL = (unsigned*)symaddr(g_BL);

    (void)in_sizes; (void)n_in; (void)out_size;

    cudaFuncSetAttribute(gemm_tc<128, 0, 0>, cudaFuncAttributeMaxDynamicSharedMemorySize, SMEM128);
    cudaFuncSetAttribute(gemm_tc<128, 0, 1>, cudaFuncAttributeMaxDynamicSharedMemorySize, SMEM128);
    cudaFuncSetAttribute(gemm_tc<128, 1, 1>, cudaFuncAttributeMaxDynamicSharedMemorySize, SMEM128);
    cudaFuncSetAttribute(gemm_tc<128, 2, 1>, cudaFuncAttributeMaxDynamicSharedMemorySize, SMEM128);
    cudaFuncSetAttribute(gemm_tc<128, 3, 1>, cudaFuncAttributeMaxDynamicSharedMemorySize, SMEM128);
    cudaFuncSetAttribute(gemm_tc<128, 4, 1>, cudaFuncAttributeMaxDynamicSharedMemorySize, SMEM128);
    cudaFuncSetAttribute(gemm_tc<128, 5, 1>, cudaFuncAttributeMaxDynamicSharedMemorySize, SMEM128);
    cudaFuncSetAttribute(gemm_tc<128, 6, 1>, cudaFuncAttributeMaxDynamicSharedMemorySize, SMEM128);
    cudaFuncSetAttribute(gemm_tc<64, 0, 1>, cudaFuncAttributeMaxDynamicSharedMemorySize, SMEM64);

    const int EW2 = (E_NUM * 32 + 255) / 256;
    const int ZB = (NN * 64 + 255) / 256;
    const long E64w = E_NUM * 64;

    // fused weight pre-split: one launch for all 12 plain matrices
    WPArr wa;
    auto setw = [&](int i, const float* W, int off, int K, int N) {
        wa.e[i].W = W;
        wa.e[i].off = off;
        wa.e[i].halfN = N / 2;
        wa.e[i].words = K * N / 2;
    };
    setw(0, tb_w0, OFF_NA, 64, 256);
    setw(1, tb_w0 + 64 * 256, OFF_NB, 64, 256);
    setw(2, tb_w1, OFF_TB1, 256, 256);
    setw(3, tb_w2, OFF_TB2, 256, 256);
    setw(4, env0_w, OFF_ENV0, 256, 320);
    setw(5, env1_w, OFF_ENV1, 256, 192);
    setw(6, lin0_sw, OFF_L0S, 128, 64);
    setw(7, lin0_vw, OFF_L0V, 128, 64);
    setw(8, lat1_w0, OFF_LA0, 384, 256);
    setw(9, lat1_w1, OFF_LA1, 256, 256);
    setw(10, fin_w0, OFF_F0, 384, 256);
    setw(11, fin_w1, OFF_F1, 256, 128);
    k_wprep_all<<<dim3(192, 12), 256>>>(wa);
    k_prep1<<<(128 * 64 + 255) / 256, 256>>>(lin1_sw, lin1_vw);

    // node precompute (A fp32)
    gemm_tc<128, 0, 0><<<dim3(2, 40, 1), 256, SMEM128>>>(node_attrs, nullptr, 64, nullptr, nullptr, 0,
        BH + OFF_NA, BL + OFF_NA, 128, An, nullptr, nullptr, NN, nullptr, nullptr, 0, 0, nullptr, nullptr, 256);
    gemm_tc<128, 0, 0><<<dim3(2, 40, 1), 256, SMEM128>>>(node_attrs, nullptr, 64, nullptr, nullptr, 0,
        BH + OFF_NB, BL + OFF_NB, 128, Bn, nullptr, nullptr, NN, nullptr, nullptr, 0, 0, nullptr, nullptr, 256);

    // first layer + cut (packed h0)
    k_first<<<E_NUM, 128>>>(radial, elen, eidx, tb_w0 + 128 * 256);

    // tb MLP
    gemm_tc<128, 1, 1><<<dim3(2, 782, 1), 256, SMEM128>>>(h0H, h0L, 256, nullptr, nullptr, 0,
        BH + OFF_TB1, BL + OFF_TB1, 128, nullptr, h1H, h1L, E_NUM, nullptr, nullptr, 0, 0, nullptr, nullptr, 256);
    gemm_tc<128, 2, 1><<<dim3(2, 782, 1), 256, SMEM128>>>(h1H, h1L, 256, nullptr, nullptr, 0,
        BH + OFF_TB2, BL + OFF_TB2, 128, lat, latH, latL, E_NUM, cut, nullptr, 0, 0, nullptr, nullptr, 256);

    // env0: fused scatter (cols 0..127) + gate/feat store (cols 128..319 -> wall[0..191])
    k_zero<<<ZB, 256>>>();
    gemm_tc<128, 6, 1><<<dim3(1, 782, 1), 256, SMEM128>>>(latH, latL, 256, nullptr, nullptr, 0,
        BH + OFF_ENV0, BL + OFF_ENV0, 160, nullptr, nullptr, nullptr, E_NUM, nullptr, nullptr, 0, 0, eidx, ang, 256);
    gemm_tc<64, 0, 1><<<dim3(3, 782, 1), 256, SMEM64>>>(latH, latL, 256, nullptr, nullptr, 0,
        BH + OFF_ENV0 + 64, BL + OFF_ENV0 + 64, 160, wall, nullptr, nullptr, E_NUM, nullptr, nullptr, 0, 0, nullptr, nullptr, 192);
    k_nodelin<<<NN, 256>>>(envlin0);
    k_tp0<<<EW2, 256>>>(ang, eidx);

    // lin0 (N=64, packed ts/tv A)
    gemm_tc<64, 0, 1><<<dim3(1, 782, 1), 256, SMEM64>>>(tsH, tsL, 128, nullptr, nullptr, 0,
        BH + OFF_L0S, BL + OFF_L0S, 32, fs1, nullptr, nullptr, E_NUM, nullptr, nullptr, 0, 0, nullptr, nullptr, 64);
    gemm_tc<64, 0, 1><<<dim3(1, 782, 3), 256, SMEM64>>>(tvH, tvL, 128, nullptr, nullptr, 0,
        BH + OFF_L0V, BL + OFF_L0V, 32, fv1, nullptr, nullptr, E_NUM, nullptr, nullptr, E64w, E64w, nullptr, nullptr, 64);

    // lat1 MLP + residual
    gemm_tc<128, 1, 1><<<dim3(2, 782, 1), 256, SMEM128>>>(latH, latL, 256, tsH, tsL, 128,
        BH + OFF_LA0, BL + OFF_LA0, 128, nullptr, h1H, h1L, E_NUM, nullptr, nullptr, 0, 0, nullptr, nullptr, 256);
    gemm_tc<128, 3, 1><<<dim3(2, 782, 1), 256, SMEM128>>>(h1H, h1L, 256, nullptr, nullptr, 0,
        BH + OFF_LA1, BL + OFF_LA1, 128, lat, latH, latL, E_NUM, cut, res_p, 0, 0, nullptr, nullptr, 256);

    // env1
    k_zero<<<ZB, 256>>>();
    gemm_tc<128, 6, 1><<<dim3(1, 782, 1), 256, SMEM128>>>(latH, latL, 256, nullptr, nullptr, 0,
        BH + OFF_ENV1, BL + OFF_ENV1, 96, nullptr, nullptr, nullptr, E_NUM, nullptr, nullptr, 0, 0, eidx, ang, 256);
    gemm_tc<64, 0, 1><<<dim3(1, 782, 1), 256, SMEM64>>>(latH, latL, 256, nullptr, nullptr, 0,
        BH + OFF_ENV1 + 64, BL + OFF_ENV1 + 64, 96, wall, nullptr, nullptr, E_NUM, nullptr, nullptr, 0, 0, nullptr, nullptr, 64);
    k_nodelin<<<NN, 256>>>(envlin1);
    k_tp1<<<EW2, 256>>>(ang, eidx);

    // lin1: sw -> fs3; vw -> out vector half
    gemm_tc<128, 0, 1><<<dim3(1, 782, 1), 256, SMEM128>>>(tsH, tsL, 128, nullptr, nullptr, 0,
        BH + OFF_SW1, BL + OFF_SW1, 64, fs3, nullptr, nullptr, E_NUM, nullptr, nullptr, 0, 0, nullptr, nullptr, 128);
    gemm_tc<128, 5, 1><<<dim3(1, 782, 3), 256, SMEM128>>>(tvH, tvL, 128, nullptr, nullptr, 0,
        BH + OFF_VW1, BL + OFF_VW1, 64, out, nullptr, nullptr, E_NUM, nullptr, nullptr, E64w, 0, nullptr, nullptr, 128);

    // fin MLP
    gemm_tc<128, 1, 1><<<dim3(2, 782, 1), 256, SMEM128>>>(latH, latL, 256, tsH, tsL, 128,
        BH + OFF_F0, BL + OFF_F0, 128, nullptr, h1H, h1L, E_NUM, nullptr, nullptr, 0, 0, nullptr, nullptr, 256);
    gemm_tc<128, 4, 1><<<dim3(1, 782, 1), 256, SMEM128>>>(h1H, h1L, 256, nullptr, nullptr, 0,
        BH + OFF_F1, BL + OFF_F1, 64, out, nullptr, nullptr, E_NUM, fs3, nullptr, 0, 0, nullptr, nullptr, 128);
}

// round 16
// speedup vs baseline: 1.1651x; 1.0109x over previous
#include <cuda_runtime.h>
#include <cuda_bf16.h>
#include <math.h>

#define E_NUM 100000
#define NN 5000

// ---------------- packed (bf16 hi/lo) scratch ----------------
__device__ __align__(16) unsigned g_h0H[E_NUM * 128];
__device__ __align__(16) unsigned g_h0L[E_NUM * 128];
__device__ __align__(16) unsigned g_h1H[E_NUM * 128];
__device__ __align__(16) unsigned g_h1L[E_NUM * 128];
__device__ __align__(16) unsigned g_latH[E_NUM * 128];
__device__ __align__(16) unsigned g_latL[E_NUM * 128];
// unified tensor product: comp0 = ts, comps 1..3 = tv
__device__ __align__(16) unsigned g_tsvH[4 * E_NUM * 64];
__device__ __align__(16) unsigned g_tsvL[4 * E_NUM * 64];
__device__ __align__(16) unsigned g_BH[320000];
__device__ __align__(16) unsigned g_BL[320000];
// fp32 scratch
__device__ __align__(16) float g_An[NN * 256];
__device__ __align__(16) float g_Bn[NN * 256];
__device__ __align__(16) float g_cut[E_NUM];
__device__ __align__(16) float g_lat[E_NUM * 256];
__device__ __align__(16) float g_wall[E_NUM * 192];
__device__ __align__(16) float g_fsv1[4 * E_NUM * 64];  // comp0 = fs1, 1..3 = fv1
__device__ __align__(16) float g_ns[NN * 64];
__device__ __align__(16) float g_nv[3 * NN * 64];
__device__ __align__(16) float g_ns2[NN * 64];
__device__ __align__(16) float g_nv2[3 * NN * 64];
__device__ __align__(16) float g_fs3[E_NUM * 128];

#define OFF_NA 0
#define OFF_NB 8192
#define OFF_TB1 16384
#define OFF_TB2 49152
#define OFF_ENV0 81920
#define OFF_ENV1 122880
#define OFF_L0S 147456
#define OFF_L0V 151552
#define OFF_LA0 155648
#define OFF_LA1 204800
#define OFF_SW1 237568
#define OFF_VW1 245760
#define OFF_F0 253952
#define OFF_F1 303104

__device__ __forceinline__ float siluf(float x) { return x / (1.0f + expf(-x)); }

__device__ __forceinline__ void bsplit(float x, unsigned short& hb, unsigned short& lb)
{
    __nv_bfloat16 h = __float2bfloat16(x);
    hb = __bfloat16_as_ushort(h);
    float hf = __uint_as_float((unsigned)hb << 16);
    lb = __bfloat16_as_ushort(__float2bfloat16(x - hf));
}
__device__ __forceinline__ unsigned pack16(unsigned short lo, unsigned short hi)
{
    return (unsigned)lo | ((unsigned)hi << 16);
}
__device__ __forceinline__ void packpair(float v0, float v1, unsigned& H, unsigned& L)
{
    unsigned short h0, l0, h1, l1;
    bsplit(v0, h0, l0);
    bsplit(v1, h1, l1);
    H = pack16(h0, h1);
    L = pack16(l0, l1);
}
__device__ __forceinline__ void cp16(unsigned d, const void* s, int sz)
{
    asm volatile("cp.async.cg.shared.global [%0], [%1], 16, %2;\n" :: "r"(d), "l"(s), "r"(sz));
}
__device__ __forceinline__ void cp_commit() { asm volatile("cp.async.commit_group;\n"); }
template <int N>
__device__ __forceinline__ void cp_wait() { asm volatile("cp.async.wait_group %0;\n" :: "n"(N)); }

#define MMA_BF16(ACC, A0, A1, A2, A3, B0, B1)                                     \
    asm volatile(                                                                 \
        "mma.sync.aligned.m16n8k16.row.col.f32.bf16.bf16.f32 "                    \
        "{%0,%1,%2,%3},{%4,%5,%6,%7},{%8,%9},{%0,%1,%2,%3};"                      \
        : "+f"((ACC)[0]), "+f"((ACC)[1]), "+f"((ACC)[2]), "+f"((ACC)[3])          \
        : "r"(A0), "r"(A1), "r"(A2), "r"(A3), "r"(B0), "r"(B1))

#define LDSM4(R, ADDR)                                                            \
    asm volatile("ldmatrix.sync.aligned.m8n8.x4.shared.b16 {%0,%1,%2,%3},[%4];"   \
                 : "=r"((R)[0]), "=r"((R)[1]), "=r"((R)[2]), "=r"((R)[3])         \
                 : "r"(ADDR))

#define LDSM4T(R0, R1, R2, R3, ADDR)                                              \
    asm volatile("ldmatrix.sync.aligned.m8n8.x4.trans.shared.b16 "                \
                 "{%0,%1,%2,%3},[%4];"                                            \
                 : "=r"(R0), "=r"(R1), "=r"(R2), "=r"(R3)                         \
                 : "r"(ADDR))

// ============ 3xBF16 GEMM, pre-split operands, NSTAGE cp.async pipeline ============
template <int BN, int EPI, int ASPLIT>
__global__ void __launch_bounds__(256, (BN == 64) ? 3 : 2) gemm_tc(
    const void* A1a, const void* A1b, int K1,
    const unsigned* __restrict__ A2H, const unsigned* __restrict__ A2L, int K2,
    const unsigned* __restrict__ BHp, const unsigned* __restrict__ BLp, int Nw,
    float* C, unsigned* CH, unsigned* CL,
    int M, const float* __restrict__ caux, const float* __restrict__ res_p,
    long strideAw, long strideC, long strideB,
    const int* __restrict__ centers, const float* __restrict__ angp, int Cld)
{
    constexpr int BM = 128, BK = 32;
    constexpr int NSTAGE = (BN == 64) ? 2 : 3;
    constexpr int WM = (BN == 64) ? 32 : 64;
    constexpr int MT = WM / 16;
    constexpr int NT = 4;
    constexpr int NWM = BM / WM;
    constexpr int AW = 20;
    constexpr int BW = BN / 2 + 4;
    constexpr int ASZ = NSTAGE * BM * AW;
    constexpr int BSZ = NSTAGE * BK * BW;
    constexpr int F4W = BN / 8;
    constexpr int RPPB = 256 / F4W;
    constexpr int NPB = BK / RPPB;

    extern __shared__ unsigned smu[];
    unsigned* AsH = smu;
    unsigned* AsL = smu + ASZ;
    unsigned* BsH = smu + 2 * ASZ;
    unsigned* BsL = smu + 2 * ASZ + BSZ;
    const unsigned baseAH = (unsigned)__cvta_generic_to_shared(AsH);
    const unsigned baseAL = (unsigned)__cvta_generic_to_shared(AsL);
    const unsigned baseBH = (unsigned)__cvta_generic_to_shared(BsH);
    const unsigned baseBL = (unsigned)__cvta_generic_to_shared(BsL);

    const int comp = blockIdx.z;
    const unsigned* A1H = (const unsigned*)A1a + (size_t)comp * strideAw;
    const unsigned* A1L = (const unsigned*)A1b + (size_t)comp * strideAw;
    const float* A1F = (const float*)A1a;
    const unsigned* BH = BHp + ((comp > 0) ? strideB : 0);
    const unsigned* BL = BLp + ((comp > 0) ? strideB : 0);
    C += (size_t)comp * ((EPI == 5) ? 1 : strideC);

    const int tid = threadIdx.x;
    const int lane = tid & 31;
    const int warp = tid >> 5;
    const int g = lane >> 2;
    const int kq = lane & 3;
    const int wm = warp & (NWM - 1);
    const int wn = warp / NWM;
    const int m0 = blockIdx.y * BM;
    const int n0w = blockIdx.x * (BN / 2);
    const int K = K1 + K2;
    const int T = K / BK;

    const int arow = (lane & 7) + ((lane >> 3) & 1) * 8;
    const int akoff = (lane >> 4) * 4;
    const int brow = (lane & 7) + ((lane >> 3) & 1) * 8;
    const int bnoff = (lane >> 4) * 4;

    float acc[MT][NT][4];
#pragma unroll
    for (int i = 0; i < MT; i++)
#pragma unroll
        for (int j = 0; j < NT; j++)
#pragma unroll
            for (int q = 0; q < 4; q++) acc[i][j][q] = 0.0f;

    auto compute = [&](int buf) {
#pragma unroll
        for (int ks = 0; ks < 2; ks++) {
            unsigned ah[MT][4], al[MT][4], bh[NT][2], bl[NT][2];
#pragma unroll
            for (int mt = 0; mt < MT; mt++) {
                unsigned offA = (unsigned)(((buf * BM + wm * WM + mt * 16 + arow) * AW
                                            + ks * 8 + akoff) * 4);
                LDSM4(ah[mt], baseAH + offA);
                LDSM4(al[mt], baseAL + offA);
            }
#pragma unroll
            for (int q = 0; q < 2; q++) {
                unsigned offB = (unsigned)(((buf * BK + ks * 16 + brow) * BW
                                            + wn * 16 + q * 8 + bnoff) * 4);
                LDSM4T(bh[2 * q][0], bh[2 * q][1], bh[2 * q + 1][0], bh[2 * q + 1][1],
                       baseBH + offB);
                LDSM4T(bl[2 * q][0], bl[2 * q][1], bl[2 * q + 1][0], bl[2 * q + 1][1],
                       baseBL + offB);
            }
#pragma unroll
            for (int mt = 0; mt < MT; mt++)
#pragma unroll
                for (int nt = 0; nt < NT; nt++) {
                    MMA_BF16(acc[mt][nt], al[mt][0], al[mt][1], al[mt][2], al[mt][3],
                             bh[nt][0], bh[nt][1]);
                    MMA_BF16(acc[mt][nt], ah[mt][0], ah[mt][1], ah[mt][2], ah[mt][3],
                             bl[nt][0], bl[nt][1]);
                    MMA_BF16(acc[mt][nt], ah[mt][0], ah[mt][1], ah[mt][2], ah[mt][3],
                             bh[nt][0], bh[nt][1]);
                }
        }
    };

    if (ASPLIT) {
        auto issue = [&](int kt, int buf) {
            int k0 = kt * BK;
            const unsigned *AH, *AL;
            int Kw, k0w;
            if (k0 < K1) { AH = A1H; AL = A1L; Kw = K1 >> 1; k0w = k0 >> 1; }
            else { AH = A2H; AL = A2L; Kw = K2 >> 1; k0w = (k0 - K1) >> 1; }
            int wc = (tid & 3) * 4;
            int rb = tid >> 2;
#pragma unroll
            for (int p = 0; p < 2; p++) {
                int row = rb + p * 64;
                int gm = m0 + row;
                int sz = (gm < M) ? 16 : 0;
                size_t so = (size_t)gm * Kw + k0w + wc;
                unsigned doff = (unsigned)(((buf * BM + row) * AW + wc) * 4);
                cp16(baseAH + doff, &AH[so], sz);
                cp16(baseAL + doff, &AL[so], sz);
            }
#pragma unroll
            for (int p = 0; p < NPB; p++) {
                int r = tid / F4W + p * RPPB;
                int c4 = (tid % F4W) * 4;
                size_t so = (size_t)(k0 + r) * Nw + n0w + c4;
                unsigned doff = (unsigned)(((buf * BK + r) * BW + c4) * 4);
                cp16(baseBH + doff, &BH[so], 16);
                cp16(baseBL + doff, &BL[so], 16);
            }
        };
#pragma unroll
        for (int s = 0; s < NSTAGE - 1; s++) {
            issue(s, s);
            cp_commit();
        }
        for (int t = 0; t < T; t++) {
            cp_wait<NSTAGE - 2>();
            __syncthreads();
            if (t + NSTAGE - 1 < T) issue(t + NSTAGE - 1, (t + NSTAGE - 1) % NSTAGE);
            cp_commit();  // ALWAYS commit (empty group in tail) so wait<N-2> drains group t
            compute(t % NSTAGE);
        }
    } else {
        float4 aF[4];
        uint4 bSH[NPB], bSL[NPB];
        auto loadRegs = [&](int kt) {
            int k0 = kt * BK;
            int ac = (tid & 7) * 4;
            int rb = tid >> 3;
#pragma unroll
            for (int p = 0; p < 4; p++) {
                int gm = m0 + rb + p * 32;
                aF[p] = (gm < M) ? *reinterpret_cast<const float4*>(&A1F[(size_t)gm * K1 + k0 + ac])
                                 : make_float4(0.f, 0.f, 0.f, 0.f);
            }
#pragma unroll
            for (int p = 0; p < NPB; p++) {
                int r = tid / F4W + p * RPPB;
                int c4 = (tid % F4W) * 4;
                bSH[p] = *reinterpret_cast<const uint4*>(&BH[(size_t)(k0 + r) * Nw + n0w + c4]);
                bSL[p] = *reinterpret_cast<const uint4*>(&BL[(size_t)(k0 + r) * Nw + n0w + c4]);
            }
        };
        auto storeStage = [&](int buf) {
            int ac = (tid & 7) * 4;
            int rb = tid >> 3;
#pragma unroll
            for (int p = 0; p < 4; p++) {
                const float* v = reinterpret_cast<const float*>(&aF[p]);
                unsigned short h[4], l[4];
#pragma unroll
                for (int j = 0; j < 4; j++) bsplit(v[j], h[j], l[j]);
                int off = (buf * BM + rb + p * 32) * AW + (ac >> 1);
                *reinterpret_cast<uint2*>(&AsH[off]) = make_uint2(pack16(h[0], h[1]), pack16(h[2], h[3]));
                *reinterpret_cast<uint2*>(&AsL[off]) = make_uint2(pack16(l[0], l[1]), pack16(l[2], l[3]));
            }
#pragma unroll
            for (int p = 0; p < NPB; p++) {
                int r = tid / F4W + p * RPPB;
                int c4 = (tid % F4W) * 4;
                int off = (buf * BK + r) * BW + c4;
                *reinterpret_cast<uint4*>(&BsH[off]) = bSH[p];
                *reinterpret_cast<uint4*>(&BsL[off]) = bSL[p];
            }
        };
        loadRegs(0);
        storeStage(0);
        __syncthreads();
        for (int t = 0; t < T; t++) {
            bool more = (t + 1 < T);
            if (more) loadRegs(t + 1);
            compute(t % NSTAGE);
            if (more) storeStage((t + 1) % NSTAGE);
            __syncthreads();
        }
    }

    float rc1 = 0.f, rc2 = 0.f;
    if (EPI == 3) {
        float av = 1.0f / (1.0f + expf(-res_p[1]));
        rc1 = sqrtf(1.0f - av);
        rc2 = sqrtf(av);
    }
#pragma unroll
    for (int mt = 0; mt < MT; mt++) {
#pragma unroll
        for (int h = 0; h < 2; h++) {
            int row = m0 + wm * WM + mt * 16 + g + h * 8;
            if (row >= M) continue;
            float rs = (EPI == 2 || EPI == 3) ? caux[row] : 0.0f;
            int cnode = 0;
            float4 sh = make_float4(0.f, 0.f, 0.f, 0.f);
            if (EPI == 6) {
                cnode = centers[row];
                sh = *reinterpret_cast<const float4*>(&angp[(size_t)row * 4]);
            }
#pragma unroll
            for (int nt = 0; nt < NT; nt++) {
                int col = n0w * 2 + wn * 32 + nt * 8 + kq * 2;
                float v0 = acc[mt][nt][2 * h];
                float v1 = acc[mt][nt][2 * h + 1];
                if (EPI == 6) {
                    int u = col >> 1;
                    atomicAdd(&g_ns[cnode * 64 + u], v0 * sh.x);
                    atomicAdd(&g_nv[cnode * 64 + u], v1 * sh.y);
                    atomicAdd(&g_nv[NN * 64 + cnode * 64 + u], v1 * sh.z);
                    atomicAdd(&g_nv[2 * NN * 64 + cnode * 64 + u], v1 * sh.w);
                    continue;
                }
                if (EPI == 1) {
                    v0 = siluf(v0);
                    v1 = siluf(v1);
                    unsigned H, L;
                    packpair(v0, v1, H, L);
                    size_t w = (size_t)row * (Cld >> 1) + (col >> 1);
                    CH[w] = H;
                    CL[w] = L;
                } else if (EPI == 2) {
                    v0 *= rs;
                    v1 *= rs;
                    *reinterpret_cast<float2*>(&C[(size_t)row * Cld + col]) = make_float2(v0, v1);
                    unsigned H, L;
                    packpair(v0, v1, H, L);
                    size_t w = (size_t)row * (Cld >> 1) + (col >> 1);
                    CH[w] = H;
                    CL[w] = L;
                } else if (EPI == 3) {
                    float2 o = *reinterpret_cast<const float2*>(&C[(size_t)row * Cld + col]);
                    v0 = rc1 * o.x + rc2 * rs * v0;
                    v1 = rc1 * o.y + rc2 * rs * v1;
                    unsigned H, L;
                    packpair(v0, v1, H, L);
                    size_t w = (size_t)row * (Cld >> 1) + (col >> 1);
                    CH[w] = H;
                    CL[w] = L;
                } else if (EPI == 4) {
                    float s0 = caux[(size_t)row * 128 + col];
                    float s1 = caux[(size_t)row * 128 + col + 1];
                    *reinterpret_cast<float2*>(&C[(size_t)row * 512 + col]) = make_float2(v0 * s0, v1 * s1);
                } else if (EPI == 5) {
                    size_t b = (size_t)row * 512 + 128 + (size_t)col * 3;
                    C[b] = v0;
                    C[b + 3] = v1;
                } else {
                    *reinterpret_cast<float2*>(&C[(size_t)row * Cld + col]) = make_float2(v0, v1);
                }
            }
        }
    }
}

// ---------------- fused weight pre-split ----------------
struct WPEnt { const float* W; int off; int halfN; int words; };
struct WPArr { WPEnt e[12]; };

__global__ void k_wprep_all(WPArr arr)
{
    WPEnt e = arr.e[blockIdx.y];
    int idx = blockIdx.x * 256 + threadIdx.x;
    if (idx >= e.words) return;
    int k = idx / e.halfN;
    int c = idx - k * e.halfN;
    unsigned hw, lw;
    packpair(e.W[(size_t)k * 2 * e.halfN + 2 * c], e.W[(size_t)k * 2 * e.halfN + 2 * c + 1], hw, lw);
    g_BH[e.off + idx] = hw;
    g_BL[e.off + idx] = lw;
}

__global__ void k_prep1(const float* __restrict__ sw, const float* __restrict__ vw)
{
    int idx = blockIdx.x * 256 + threadIdx.x;
    if (idx >= 128 * 64) return;
    int r = idx >> 6, c = idx & 63;
    int i = r >> 6, u = r & 63;
    int col0 = 2 * c;
    int o = col0 >> 6, v = col0 & 63;
    size_t s = ((size_t)(i * 2 + o) * 64 + u) * 64 + v;
    unsigned hw, lw;
    packpair(sw[s], sw[s + 1], hw, lw);
    g_BH[OFF_SW1 + idx] = hw;
    g_BL[OFF_SW1 + idx] = lw;
    packpair(vw[s], vw[s + 1], hw, lw);
    g_BH[OFF_VW1 + idx] = hw;
    g_BL[OFF_VW1 + idx] = lw;
}

// ---------------- first layer (packed h0 out) ----------------
__global__ void k_first(const float* __restrict__ radial, const float* __restrict__ elen,
                        const int* __restrict__ eidx, const float* __restrict__ w0r)
{
    int e = blockIdx.x;
    int t = threadIdx.x;  // 128
    __shared__ float r[8];
    if (t < 8) r[t] = radial[e * 8 + t];
    if (t == 0) {
        float x = elen[e] * 0.2f;
        float x2 = x * x;
        float x6 = x2 * x2 * x2;
        float o = 1.0f - 28.0f * x6 + 48.0f * x6 * x - 21.0f * x6 * x2;
        g_cut[e] = (x < 1.0f) ? o : 0.0f;
    }
    __syncthreads();
    int c = eidx[e];
    int n = eidx[E_NUM + e];
    float a0 = g_An[c * 256 + 2 * t] + g_Bn[n * 256 + 2 * t];
    float a1 = g_An[c * 256 + 2 * t + 1] + g_Bn[n * 256 + 2 * t + 1];
#pragma unroll
    for (int j = 0; j < 8; j++) {
        a0 = fmaf(r[j], w0r[j * 256 + 2 * t], a0);
        a1 = fmaf(r[j], w0r[j * 256 + 2 * t + 1], a1);
    }
    unsigned H, L;
    packpair(siluf(a0), siluf(a1), H, L);
    g_h0H[(size_t)e * 128 + t] = H;
    g_h0L[(size_t)e * 128 + t] = L;
}

__global__ void k_zero()
{
    int i = blockIdx.x * 256 + threadIdx.x;
    if (i < NN * 64) {
        g_ns[i] = 0.f;
        g_nv[i] = 0.f;
        g_nv[NN * 64 + i] = 0.f;
        g_nv[2 * NN * 64 + i] = 0.f;
    }
}

__global__ void k_nodelin(const float* __restrict__ W)
{
    int nn = blockIdx.x;
    int t = threadIdx.x;
    __shared__ float sin_[256];
    int ch = t >> 6, v = t & 63;
    float val = (ch == 0) ? g_ns[nn * 64 + v] : g_nv[(ch - 1) * NN * 64 + nn * 64 + v];
    sin_[t] = val * 0.05f;
    __syncthreads();
    const float* Wm = W + (ch == 0 ? 0 : 64 * 64);
    float acc = 0.f;
#pragma unroll
    for (int u = 0; u < 64; u++) acc = fmaf(sin_[ch * 64 + u], Wm[u * 64 + v], acc);
    if (ch == 0) g_ns2[nn * 64 + v] = acc;
    else g_nv2[(ch - 1) * NN * 64 + nn * 64 + v] = acc;
}

__device__ __forceinline__ void tp_pack(int e, int c, int cn,
                                        float f0, float fx0, float fy0, float fz0,
                                        float f1, float fx1, float fy1, float fz1)
{
    const float IS3 = 0.57735026918962576f;
    const size_t CW = (size_t)E_NUM * 64;
    int u0 = 2 * c, u1 = 2 * c + 1;
    float s20 = g_ns2[cn * 64 + u0], s21 = g_ns2[cn * 64 + u1];
    float vx0 = g_nv2[cn * 64 + u0], vx1 = g_nv2[cn * 64 + u1];
    float vy0 = g_nv2[NN * 64 + cn * 64 + u0], vy1 = g_nv2[NN * 64 + cn * 64 + u1];
    float vz0 = g_nv2[2 * NN * 64 + cn * 64 + u0], vz1 = g_nv2[2 * NN * 64 + cn * 64 + u1];
    size_t b = (size_t)e * 64 + c;
    unsigned H, L;
    packpair(f0 * s20, f1 * s21, H, L);
    g_tsvH[b] = H; g_tsvL[b] = L;
    packpair((fx0 * vx0 + fy0 * vy0 + fz0 * vz0) * IS3,
             (fx1 * vx1 + fy1 * vy1 + fz1 * vz1) * IS3, H, L);
    g_tsvH[b + 32] = H; g_tsvL[b + 32] = L;
    packpair(f0 * vx0 * IS3, f1 * vx1 * IS3, H, L);
    g_tsvH[CW + b] = H; g_tsvL[CW + b] = L;
    packpair(fx0 * s20 * IS3, fx1 * s21 * IS3, H, L);
    g_tsvH[CW + b + 32] = H; g_tsvL[CW + b + 32] = L;
    packpair(f0 * vy0 * IS3, f1 * vy1 * IS3, H, L);
    g_tsvH[2 * CW + b] = H; g_tsvL[2 * CW + b] = L;
    packpair(fy0 * s20 * IS3, fy1 * s21 * IS3, H, L);
    g_tsvH[2 * CW + b + 32] = H; g_tsvL[2 * CW + b + 32] = L;
    packpair(f0 * vz0 * IS3, f1 * vz1 * IS3, H, L);
    g_tsvH[3 * CW + b] = H; g_tsvL[3 * CW + b] = L;
    packpair(fz0 * s20 * IS3, fz1 * s21 * IS3, H, L);
    g_tsvH[3 * CW + b + 32] = H; g_tsvL[3 * CW + b + 32] = L;
}

__global__ void k_tp0(const float* __restrict__ ang, const int* __restrict__ center)
{
    int idx = blockIdx.x * blockDim.x + threadIdx.x;
    if (idx >= E_NUM * 32) return;
    int e = idx >> 5, c = idx & 31;
    int u0 = 2 * c, u1 = 2 * c + 1;
    float4 sh = *reinterpret_cast<const float4*>(&ang[e * 4]);
    const float* w = &g_wall[(size_t)e * 192];
    float gt0 = w[u0], gt1 = w[u1];
    float wf00 = w[64 + 2 * u0], wf10 = w[65 + 2 * u0];
    float wf01 = w[64 + 2 * u1], wf11 = w[65 + 2 * u1];
    tp_pack(e, c, center[e],
            wf00 * sh.x * gt0, wf10 * sh.y * gt0, wf10 * sh.z * gt0, wf10 * sh.w * gt0,
            wf01 * sh.x * gt1, wf11 * sh.y * gt1, wf11 * sh.z * gt1, wf11 * sh.w * gt1);
}

__global__ void k_tp1(const float* __restrict__ ang, const int* __restrict__ center)
{
    int idx = blockIdx.x * blockDim.x + threadIdx.x;
    if (idx >= E_NUM * 32) return;
    int e = idx >> 5, c = idx & 31;
    int u0 = 2 * c, u1 = 2 * c + 1;
    const size_t CW = (size_t)E_NUM * 64;
    float gt0 = g_wall[(size_t)e * 64 + u0], gt1 = g_wall[(size_t)e * 64 + u1];
    size_t b0 = (size_t)e * 64 + u0, b1 = (size_t)e * 64 + u1;
    tp_pack(e, c, center[e],
            g_fsv1[b0] * gt0, g_fsv1[CW + b0] * gt0,
            g_fsv1[2 * CW + b0] * gt0, g_fsv1[3 * CW + b0] * gt0,
            g_fsv1[b1] * gt1, g_fsv1[CW + b1] * gt1,
            g_fsv1[2 * CW + b1] * gt1, g_fsv1[3 * CW + b1] * gt1);
}

// ---------------- host launch ----------------
template <typename T>
static void* symaddr(const T& sym)
{
    void* p = nullptr;
    cudaGetSymbolAddress(&p, sym);
    return p;
}

static const int SMEM64 = (2 * (2 * 128 * 20) + 2 * (2 * 32 * 36)) * 4;    // 59392
static const int SMEM128 = (2 * (3 * 128 * 20) + 2 * (3 * 32 * 68)) * 4;   // 113664

extern "C" void kernel_launch(void* const* d_in, const int* in_sizes, int n_in,
                              void* d_out, int out_size)
{
    const float* node_attrs = (const float*)d_in[0];
    const float* radial = (const float*)d_in[1];
    const float* ang = (const float*)d_in[2];
    const float* elen = (const float*)d_in[3];
    const int* eidx = (const int*)d_in[4];
    const float* tb_w0 = (const float*)d_in[5];
    const float* tb_w1 = (const float*)d_in[6];
    const float* tb_w2 = (const float*)d_in[7];
    const float* lat1_w0 = (const float*)d_in[8];
    const float* lat1_w1 = (const float*)d_in[9];
    const float* env0_w = (const float*)d_in[10];
    const float* env1_w = (const float*)d_in[11];
    const float* envlin0 = (const float*)d_in[12];
    const float* envlin1 = (const float*)d_in[13];
    const float* lin0_sw = (const float*)d_in[14];
    const float* lin0_vw = (const float*)d_in[15];
    const float* lin1_sw = (const float*)d_in[16];
    const float* lin1_vw = (const float*)d_in[17];
    const float* fin_w0 = (const float*)d_in[18];
    const float* fin_w1 = (const float*)d_in[19];
    const float* res_p = (const float*)d_in[20];
    float* out = (float*)d_out;

    float* An = (float*)symaddr(g_An);
    float* Bn = (float*)symaddr(g_Bn);
    float* cut = (float*)symaddr(g_cut);
    float* lat = (float*)symaddr(g_lat);
    float* wall = (float*)symaddr(g_wall);
    float* fsv1 = (float*)symaddr(g_fsv1);
    float* fs3 = (float*)symaddr(g_fs3);
    unsigned* h0H = (unsigned*)symaddr(g_h0H);
    unsigned* h0L = (unsigned*)symaddr(g_h0L);
    unsigned* h1H = (unsigned*)symaddr(g_h1H);
    unsigned* h1L = (unsigned*)symaddr(g_h1L);
    unsigned* latH = (unsigned*)symaddr(g_latH);
    unsigned* latL = (unsigned*)symaddr(g_latL);
    unsigned* tsvH = (unsigned*)symaddr(g_tsvH);
    unsigned* tsvL = (unsigned*)symaddr(g_tsvL);
    unsigned* BH = (unsigned*)symaddr(g_BH);
    unsigned* BL = (unsigned*)symaddr(g_BL);

    (void)in_sizes; (void)n_in; (void)out_size;

    cudaFuncSetAttribute(gemm_tc<128, 0, 0>, cudaFuncAttributeMaxDynamicSharedMemorySize, SMEM128);
    cudaFuncSetAttribute(gemm_tc<128, 0, 1>, cudaFuncAttributeMaxDynamicSharedMemorySize, SMEM128);
    cudaFuncSetAttribute(gemm_tc<128, 1, 1>, cudaFuncAttributeMaxDynamicSharedMemorySize, SMEM128);
    cudaFuncSetAttribute(gemm_tc<128, 2, 1>, cudaFuncAttributeMaxDynamicSharedMemorySize, SMEM128);
    cudaFuncSetAttribute(gemm_tc<128, 3, 1>, cudaFuncAttributeMaxDynamicSharedMemorySize, SMEM128);
    cudaFuncSetAttribute(gemm_tc<128, 4, 1>, cudaFuncAttributeMaxDynamicSharedMemorySize, SMEM128);
    cudaFuncSetAttribute(gemm_tc<128, 5, 1>, cudaFuncAttributeMaxDynamicSharedMemorySize, SMEM128);
    cudaFuncSetAttribute(gemm_tc<128, 6, 1>, cudaFuncAttributeMaxDynamicSharedMemorySize, SMEM128);
    cudaFuncSetAttribute(gemm_tc<64, 0, 1>, cudaFuncAttributeMaxDynamicSharedMemorySize, SMEM64);

    const int EW2 = (E_NUM * 32 + 255) / 256;
    const int ZB = (NN * 64 + 255) / 256;
    const long E64w = E_NUM * 64;

    // fused weight pre-split
    WPArr wa;
    auto setw = [&](int i, const float* W, int off, int K, int N) {
        wa.e[i].W = W;
        wa.e[i].off = off;
        wa.e[i].halfN = N / 2;
        wa.e[i].words = K * N / 2;
    };
    setw(0, tb_w0, OFF_NA, 64, 256);
    setw(1, tb_w0 + 64 * 256, OFF_NB, 64, 256);
    setw(2, tb_w1, OFF_TB1, 256, 256);
    setw(3, tb_w2, OFF_TB2, 256, 256);
    setw(4, env0_w, OFF_ENV0, 256, 320);
    setw(5, env1_w, OFF_ENV1, 256, 192);
    setw(6, lin0_sw, OFF_L0S, 128, 64);
    setw(7, lin0_vw, OFF_L0V, 128, 64);
    setw(8, lat1_w0, OFF_LA0, 384, 256);
    setw(9, lat1_w1, OFF_LA1, 256, 256);
    setw(10, fin_w0, OFF_F0, 384, 256);
    setw(11, fin_w1, OFF_F1, 256, 128);
    k_wprep_all<<<dim3(192, 12), 256>>>(wa);
    k_prep1<<<(128 * 64 + 255) / 256, 256>>>(lin1_sw, lin1_vw);

    // node precompute (A fp32)
    gemm_tc<128, 0, 0><<<dim3(2, 40, 1), 256, SMEM128>>>(node_attrs, nullptr, 64, nullptr, nullptr, 0,
        BH + OFF_NA, BL + OFF_NA, 128, An, nullptr, nullptr, NN, nullptr, nullptr, 0, 0, 0, nullptr, nullptr, 256);
    gemm_tc<128, 0, 0><<<dim3(2, 40, 1), 256, SMEM128>>>(node_attrs, nullptr, 64, nullptr, nullptr, 0,
        BH + OFF_NB, BL + OFF_NB, 128, Bn, nullptr, nullptr, NN, nullptr, nullptr, 0, 0, 0, nullptr, nullptr, 256);

    // first layer + cut (packed h0)
    k_first<<<E_NUM, 128>>>(radial, elen, eidx, tb_w0 + 128 * 256);

    // tb MLP
    gemm_tc<128, 1, 1><<<dim3(2, 782, 1), 256, SMEM128>>>(h0H, h0L, 256, nullptr, nullptr, 0,
        BH + OFF_TB1, BL + OFF_TB1, 128, nullptr, h1H, h1L, E_NUM, nullptr, nullptr, 0, 0, 0, nullptr, nullptr, 256);
    gemm_tc<128, 2, 1><<<dim3(2, 782, 1), 256, SMEM128>>>(h1H, h1L, 256, nullptr, nullptr, 0,
        BH + OFF_TB2, BL + OFF_TB2, 128, lat, latH, latL, E_NUM, cut, nullptr, 0, 0, 0, nullptr, nullptr, 256);

    // env0: fused scatter (cols 0..127) + gate/feat store
    k_zero<<<ZB, 256>>>();
    gemm_tc<128, 6, 1><<<dim3(1, 782, 1), 256, SMEM128>>>(latH, latL, 256, nullptr, nullptr, 0,
        BH + OFF_ENV0, BL + OFF_ENV0, 160, nullptr, nullptr, nullptr, E_NUM, nullptr, nullptr, 0, 0, 0, eidx, ang, 256);
    gemm_tc<64, 0, 1><<<dim3(3, 782, 1), 256, SMEM64>>>(latH, latL, 256, nullptr, nullptr, 0,
        BH + OFF_ENV0 + 64, BL + OFF_ENV0 + 64, 160, wall, nullptr, nullptr, E_NUM, nullptr, nullptr, 0, 0, 0, nullptr, nullptr, 192);
    k_nodelin<<<NN, 256>>>(envlin0);
    k_tp0<<<EW2, 256>>>(ang, eidx);

    // lin0: single launch z=4 (comp0: ts@sw -> fsv1[0]; comps1..3: tv@vw -> fsv1[c])
    gemm_tc<64, 0, 1><<<dim3(1, 782, 4), 256, SMEM64>>>(tsvH, tsvL, 128, nullptr, nullptr, 0,
        BH + OFF_L0S, BL + OFF_L0S, 32, fsv1, nullptr, nullptr, E_NUM, nullptr, nullptr,
        E64w, E64w, OFF_L0V - OFF_L0S, nullptr, nullptr, 64);

    // lat1 MLP + residual
    gemm_tc<128, 1, 1><<<dim3(2, 782, 1), 256, SMEM128>>>(latH, latL, 256, tsvH, tsvL, 128,
        BH + OFF_LA0, BL + OFF_LA0, 128, nullptr, h1H, h1L, E_NUM, nullptr, nullptr, 0, 0, 0, nullptr, nullptr, 256);
    gemm_tc<128, 3, 1><<<dim3(2, 782, 1), 256, SMEM128>>>(h1H, h1L, 256, nullptr, nullptr, 0,
        BH + OFF_LA1, BL + OFF_LA1, 128, lat, latH, latL, E_NUM, cut, res_p, 0, 0, 0, nullptr, nullptr, 256);

    // env1
    k_zero<<<ZB, 256>>>();
    gemm_tc<128, 6, 1><<<dim3(1, 782, 1), 256, SMEM128>>>(latH, latL, 256, nullptr, nullptr, 0,
        BH + OFF_ENV1, BL + OFF_ENV1, 96, nullptr, nullptr, nullptr, E_NUM, nullptr, nullptr, 0, 0, 0, eidx, ang, 256);
    gemm_tc<64, 0, 1><<<dim3(1, 782, 1), 256, SMEM64>>>(latH, latL, 256, nullptr, nullptr, 0,
        BH + OFF_ENV1 + 64, BL + OFF_ENV1 + 64, 96, wall, nullptr, nullptr, E_NUM, nullptr, nullptr, 0, 0, 0, nullptr, nullptr, 64);
    k_nodelin<<<NN, 256>>>(envlin1);
    k_tp1<<<EW2, 256>>>(ang, eidx);

    // lin1: sw (ts) -> fs3; vw (tv comps) -> out vector half
    gemm_tc<128, 0, 1><<<dim3(1, 782, 1), 256, SMEM128>>>(tsvH, tsvL, 128, nullptr, nullptr, 0,
        BH + OFF_SW1, BL + OFF_SW1, 64, fs3, nullptr, nullptr, E_NUM, nullptr, nullptr, 0, 0, 0, nullptr, nullptr, 128);
    gemm_tc<128, 5, 1><<<dim3(1, 782, 3), 256, SMEM128>>>(tsvH + E64w, tsvL + E64w, 128, nullptr, nullptr, 0,
        BH + OFF_VW1, BL + OFF_VW1, 64, out, nullptr, nullptr, E_NUM, nullptr, nullptr, E64w, 0, 0, nullptr, nullptr, 128);

    // fin MLP
    gemm_tc<128, 1, 1><<<dim3(2, 782, 1), 256, SMEM128>>>(latH, latL, 256, tsvH, tsvL, 128,
        BH + OFF_F0, BL + OFF_F0, 128, nullptr, h1H, h1L, E_NUM, nullptr, nullptr, 0, 0, 0, nullptr, nullptr, 256);
    gemm_tc<128, 4, 1><<<dim3(1, 782, 1), 256, SMEM128>>>(h1H, h1L, 256, nullptr, nullptr, 0,
        BH + OFF_F1, BL + OFF_F1, 64, out, nullptr, nullptr, E_NUM, fs3, nullptr, 0, 0, 0, nullptr, nullptr, 128);
}